// round 5
// baseline (speedup 1.0000x reference)
#include <cuda_runtime.h>
#include <cstdint>

namespace {
constexpr int B = 4, S = 2048, D = 512, H = 8, DK = 64;
}

// Scratch (allocation-free rule: __device__ globals)
__device__ float g_Q[(size_t)B * S * D];
__device__ float g_K[(size_t)B * S * D];
__device__ float g_V[(size_t)B * S * D];
__device__ float g_C[(size_t)B * S * D];
__device__ float g_att[(size_t)B * H * S * S];
// Split-softmax partials: per (row, 32-col warp tile)
__device__ float g_pmax[(size_t)B * H * S * 64];
__device__ float g_psum[(size_t)B * H * S * 64];
__device__ float g_rowM[(size_t)B * H * S];
__device__ float g_rowInv[(size_t)B * H * S];

// ============================================================================
// Warp-level tf32 MMA helpers (portable PTX — works on compute_103)
// ============================================================================
__device__ __forceinline__ uint32_t f2tf32(float x) {
    uint32_t u;
    asm("cvt.rna.tf32.f32 %0, %1;" : "=r"(u) : "f"(x));
    return u;
}
__device__ __forceinline__ void split_tf32(float x, uint32_t& hi, uint32_t& lo) {
    hi = f2tf32(x);
    lo = f2tf32(x - __uint_as_float(hi));
}
__device__ __forceinline__ void split4(float4 v, uint4& hi, uint4& lo) {
    split_tf32(v.x, hi.x, lo.x);
    split_tf32(v.y, hi.y, lo.y);
    split_tf32(v.z, hi.z, lo.z);
    split_tf32(v.w, hi.w, lo.w);
}
__device__ __forceinline__ void mma_tf32(float c[4], const uint32_t a[4], const uint32_t b[2]) {
    asm volatile(
        "mma.sync.aligned.m16n8k8.row.col.f32.tf32.tf32.f32 "
        "{%0,%1,%2,%3}, {%4,%5,%6,%7}, {%8,%9}, {%0,%1,%2,%3};"
        : "+f"(c[0]), "+f"(c[1]), "+f"(c[2]), "+f"(c[3])
        : "r"(a[0]), "r"(a[1]), "r"(a[2]), "r"(a[3]), "r"(b[0]), "r"(b[1]));
}

// ============================================================================
// Projection GEMM via mma.sync tf32 (3xTF32), A pre-split in SMEM:
//   Y[M,512] = X[M,512] @ W[512,512]^T + bias   (M = 8192)
// CTA: 128(m) x 128(n), 256 thr = 8 warps (2m x 4n), K-chunk 64.
// ============================================================================
namespace {
constexpr int GM_STRIDE = 68;
constexpr int GM_XHI = 0;
constexpr int GM_XLO = 128 * GM_STRIDE;
constexpr int GM_WS  = 2 * 128 * GM_STRIDE;
constexpr int SMEM_GEMM = 3 * 128 * GM_STRIDE * 4;     // 104,448 bytes
}

__global__ void __launch_bounds__(256) gemm_mma(
    const float* __restrict__ X, const float* __restrict__ W,
    const float* __restrict__ bias, float* __restrict__ Y)
{
    extern __shared__ float sm[];
    uint32_t* Xhi = reinterpret_cast<uint32_t*>(sm) + GM_XHI;
    uint32_t* Xlo = reinterpret_cast<uint32_t*>(sm) + GM_XLO;
    float*    Ws  = sm + GM_WS;

    const int t = threadIdx.x, lane = t & 31, wid = t >> 5;
    const int g = lane >> 2, tig = lane & 3;
    const int wm = wid & 1, wn = wid >> 1;
    const int m0 = blockIdx.y * 128, n0 = blockIdx.x * 128;

    float acc[4][4][4] = {};

    for (int kc = 0; kc < 512; kc += 64) {
#pragma unroll
        for (int i = t; i < 2048; i += 256) {
            const int row = i >> 4, c4 = (i & 15) * 4;
            float4 xv = *reinterpret_cast<const float4*>(&X[(size_t)(m0 + row) * 512 + kc + c4]);
            float4 wv = *reinterpret_cast<const float4*>(&W[(size_t)(n0 + row) * 512 + kc + c4]);
            uint4 hi, lo;
            split4(xv, hi, lo);
            *reinterpret_cast<uint4*>(&Xhi[row * GM_STRIDE + c4]) = hi;
            *reinterpret_cast<uint4*>(&Xlo[row * GM_STRIDE + c4]) = lo;
            *reinterpret_cast<float4*>(&Ws[row * GM_STRIDE + c4]) = wv;
        }
        __syncthreads();

#pragma unroll
        for (int ks = 0; ks < 8; ks++) {
            const int kk = ks * 8;
            uint32_t ahi[4][4], alo[4][4];
#pragma unroll
            for (int i = 0; i < 4; i++) {
                const int r0 = (wm * 64 + i * 16 + g) * GM_STRIDE;
                const int r1 = r0 + 8 * GM_STRIDE;
                ahi[i][0] = Xhi[r0 + kk + tig];     alo[i][0] = Xlo[r0 + kk + tig];
                ahi[i][1] = Xhi[r1 + kk + tig];     alo[i][1] = Xlo[r1 + kk + tig];
                ahi[i][2] = Xhi[r0 + kk + tig + 4]; alo[i][2] = Xlo[r0 + kk + tig + 4];
                ahi[i][3] = Xhi[r1 + kk + tig + 4]; alo[i][3] = Xlo[r1 + kk + tig + 4];
            }
#pragma unroll
            for (int j = 0; j < 4; j++) {
                const int nr = (wn * 32 + j * 8 + g) * GM_STRIDE;
                uint32_t bhi[2], blo[2];
                split_tf32(Ws[nr + kk + tig],     bhi[0], blo[0]);
                split_tf32(Ws[nr + kk + tig + 4], bhi[1], blo[1]);
#pragma unroll
                for (int i = 0; i < 4; i++) {
                    mma_tf32(acc[i][j], ahi[i], bhi);
                    mma_tf32(acc[i][j], alo[i], bhi);
                    mma_tf32(acc[i][j], ahi[i], blo);
                }
            }
        }
        __syncthreads();
    }

#pragma unroll
    for (int i = 0; i < 4; i++) {
        const int row0 = m0 + wm * 64 + i * 16 + g;
#pragma unroll
        for (int j = 0; j < 4; j++) {
            const int col = n0 + wn * 32 + j * 8 + 2 * tig;
            const float b0 = __ldg(bias + col), b1 = __ldg(bias + col + 1);
            float2 o;
            o.x = acc[i][j][0] + b0; o.y = acc[i][j][1] + b1;
            *reinterpret_cast<float2*>(&Y[(size_t)row0 * 512 + col]) = o;
            o.x = acc[i][j][2] + b0; o.y = acc[i][j][3] + b1;
            *reinterpret_cast<float2*>(&Y[(size_t)(row0 + 8) * 512 + col]) = o;
        }
    }
}

// ============================================================================
// Scores via mma.sync tf32 (3xTF32), Q pre-split in SMEM.
// Writes masked+biased logits to att AND per-(row, 32-col) (max, sumexp).
// ============================================================================
namespace {
constexpr int SC_STRIDE = 68;
constexpr int SC_QHI = 0;
constexpr int SC_QLO = 128 * SC_STRIDE;
constexpr int SC_KS  = 2 * 128 * SC_STRIDE;
constexpr int SMEM_SCORES = 3 * 128 * SC_STRIDE * 4;   // 104,448 bytes
}

__global__ void __launch_bounds__(256) scores_mma(
    const float* __restrict__ Q, const float* __restrict__ K,
    const int* __restrict__ mask, const float* __restrict__ is_org,
    const float* __restrict__ Worg, const float* __restrict__ borg,
    float* __restrict__ att, float* __restrict__ pmax, float* __restrict__ psum)
{
    extern __shared__ float sm[];
    uint32_t* Qhi = reinterpret_cast<uint32_t*>(sm) + SC_QHI;
    uint32_t* Qlo = reinterpret_cast<uint32_t*>(sm) + SC_QLO;
    float*    Ks  = sm + SC_KS;

    const int t = threadIdx.x, lane = t & 31, wid = t >> 5;
    const int g = lane >> 2, tig = lane & 3;
    const int wm = wid & 1, wn = wid >> 1;
    const int bh = blockIdx.z, b = bh >> 3, h = bh & 7;
    const int q0 = blockIdx.y * 128, k0g = blockIdx.x * 128;

    const float* Qg = Q + ((size_t)(b * S + q0)) * D + h * DK;
    const float* Kg = K + ((size_t)(b * S + k0g)) * D + h * DK;

#pragma unroll
    for (int i = t; i < 2048; i += 256) {
        const int row = i >> 4, c4 = (i & 15) * 4;
        float4 qv = *reinterpret_cast<const float4*>(Qg + (size_t)row * D + c4);
        float4 kv = *reinterpret_cast<const float4*>(Kg + (size_t)row * D + c4);
        uint4 hi, lo;
        split4(qv, hi, lo);
        *reinterpret_cast<uint4*>(&Qhi[row * SC_STRIDE + c4]) = hi;
        *reinterpret_cast<uint4*>(&Qlo[row * SC_STRIDE + c4]) = lo;
        *reinterpret_cast<float4*>(&Ks[row * SC_STRIDE + c4]) = kv;
    }
    __syncthreads();

    float acc[4][4][4] = {};

#pragma unroll
    for (int ks = 0; ks < 8; ks++) {
        const int kk = ks * 8;
        uint32_t ahi[4][4], alo[4][4];
#pragma unroll
        for (int i = 0; i < 4; i++) {
            const int r0 = (wm * 64 + i * 16 + g) * SC_STRIDE;
            const int r1 = r0 + 8 * SC_STRIDE;
            ahi[i][0] = Qhi[r0 + kk + tig];     alo[i][0] = Qlo[r0 + kk + tig];
            ahi[i][1] = Qhi[r1 + kk + tig];     alo[i][1] = Qlo[r1 + kk + tig];
            ahi[i][2] = Qhi[r0 + kk + tig + 4]; alo[i][2] = Qlo[r0 + kk + tig + 4];
            ahi[i][3] = Qhi[r1 + kk + tig + 4]; alo[i][3] = Qlo[r1 + kk + tig + 4];
        }
#pragma unroll
        for (int j = 0; j < 4; j++) {
            const int nr = (wn * 32 + j * 8 + g) * SC_STRIDE;
            uint32_t bhi[2], blo[2];
            split_tf32(Ks[nr + kk + tig],     bhi[0], blo[0]);
            split_tf32(Ks[nr + kk + tig + 4], bhi[1], blo[1]);
#pragma unroll
            for (int i = 0; i < 4; i++) {
                mma_tf32(acc[i][j], ahi[i], bhi);
                mma_tf32(acc[i][j], alo[i], bhi);
                mma_tf32(acc[i][j], ahi[i], blo);
            }
        }
    }

    // Finalize logits in-register: scale + organic + mask
    const float worg = __ldg(Worg + h), bog = __ldg(borg + h);
    float og[4][2];
#pragma unroll
    for (int i = 0; i < 4; i++) {
#pragma unroll
        for (int hh = 0; hh < 2; hh++) {
            const int row = q0 + wm * 64 + i * 16 + g + hh * 8;
            og[i][hh] = __ldg(is_org + b * S + row) * worg + bog;
        }
    }
    int2 mj[4];
#pragma unroll
    for (int j = 0; j < 4; j++) {
        const int col = k0g + wn * 32 + j * 8 + 2 * tig;
        mj[j] = *reinterpret_cast<const int2*>(mask + b * S + col);
    }
#pragma unroll
    for (int i = 0; i < 4; i++) {
#pragma unroll
        for (int j = 0; j < 4; j++) {
            float v;
            v = acc[i][j][0] * 0.125f + og[i][0]; acc[i][j][0] = mj[j].x ? v : -1e9f;
            v = acc[i][j][1] * 0.125f + og[i][0]; acc[i][j][1] = mj[j].y ? v : -1e9f;
            v = acc[i][j][2] * 0.125f + og[i][1]; acc[i][j][2] = mj[j].x ? v : -1e9f;
            v = acc[i][j][3] * 0.125f + og[i][1]; acc[i][j][3] = mj[j].y ? v : -1e9f;
        }
    }

    // Store logits
#pragma unroll
    for (int i = 0; i < 4; i++) {
        const int row0 = q0 + wm * 64 + i * 16 + g;
#pragma unroll
        for (int j = 0; j < 4; j++) {
            const int col = k0g + wn * 32 + j * 8 + 2 * tig;
            float2 o;
            o.x = acc[i][j][0]; o.y = acc[i][j][1];
            *reinterpret_cast<float2*>(&att[((size_t)bh * S + row0) * S + col]) = o;
            o.x = acc[i][j][2]; o.y = acc[i][j][3];
            *reinterpret_cast<float2*>(&att[((size_t)bh * S + row0 + 8) * S + col]) = o;
        }
    }

    // Per-(row, 32-col warp tile) max & sumexp partials
    const int kwarp = blockIdx.x * 4 + wn;   // 0..63
#pragma unroll
    for (int i = 0; i < 4; i++) {
#pragma unroll
        for (int hh = 0; hh < 2; hh++) {
            float m = -1e30f;
#pragma unroll
            for (int j = 0; j < 4; j++) {
                m = fmaxf(m, fmaxf(acc[i][j][hh * 2], acc[i][j][hh * 2 + 1]));
            }
            m = fmaxf(m, __shfl_xor_sync(0xffffffffu, m, 1));
            m = fmaxf(m, __shfl_xor_sync(0xffffffffu, m, 2));
            float s = 0.0f;
#pragma unroll
            for (int j = 0; j < 4; j++) {
                s += __expf(acc[i][j][hh * 2] - m) + __expf(acc[i][j][hh * 2 + 1] - m);
            }
            s += __shfl_xor_sync(0xffffffffu, s, 1);
            s += __shfl_xor_sync(0xffffffffu, s, 2);
            if (tig == 0) {
                const size_t prow = (size_t)bh * S + q0 + wm * 64 + i * 16 + g + hh * 8;
                pmax[prow * 64 + kwarp] = m;
                psum[prow * 64 + kwarp] = s;
            }
        }
    }
}

// ============================================================================
// Row-stat reduce: 64 partials per row -> (M, 1/sum). One warp per row.
// ============================================================================
__global__ void __launch_bounds__(256) reduce_rows(
    const float* __restrict__ pmax, const float* __restrict__ psum,
    float* __restrict__ rowM, float* __restrict__ rowInv)
{
    const int wid = threadIdx.x >> 5, lane = threadIdx.x & 31;
    const size_t row = (size_t)blockIdx.x * 8 + wid;
    const float m0 = pmax[row * 64 + lane];
    const float m1 = pmax[row * 64 + lane + 32];
    float m = fmaxf(m0, m1);
#pragma unroll
    for (int o = 16; o; o >>= 1) m = fmaxf(m, __shfl_xor_sync(0xffffffffu, m, o));
    float s = psum[row * 64 + lane] * __expf(m0 - m)
            + psum[row * 64 + lane + 32] * __expf(m1 - m);
#pragma unroll
    for (int o = 16; o; o >>= 1) s += __shfl_xor_sync(0xffffffffu, s, o);
    if (lane == 0) {
        rowM[row] = m;
        rowInv[row] = 1.0f / s;
    }
}

// ============================================================================
// AV via mma.sync tf32 (3xTF32) with fused softmax normalization.
// Reads logits, computes p = exp(x-M)*invS, writes p back to att, MMA with V.
// V pre-split in SMEM.
// ============================================================================
namespace {
constexpr int AV_STRIDE = 68;
constexpr int AV_AS  = 0;                                   // float [128][68]
constexpr int AV_VHI = 128 * AV_STRIDE;                     // uint [64][68]
constexpr int AV_VLO = AV_VHI + 64 * AV_STRIDE;
constexpr int AV_RM  = AV_VLO + 64 * AV_STRIDE;             // float [128]
constexpr int AV_RI  = AV_RM + 128;                         // float [128]
constexpr int SMEM_AV = (AV_RI + 128) * 4;                  // 71,680 bytes
}

__global__ void __launch_bounds__(256) av_mma(
    float* __restrict__ att, const float* __restrict__ V,
    const float* __restrict__ rowM, const float* __restrict__ rowInv,
    float* __restrict__ C)
{
    extern __shared__ float sm[];
    float*    As  = sm + AV_AS;
    uint32_t* Vhi = reinterpret_cast<uint32_t*>(sm) + AV_VHI;
    uint32_t* Vlo = reinterpret_cast<uint32_t*>(sm) + AV_VLO;
    float*    Rm  = sm + AV_RM;
    float*    Ri  = sm + AV_RI;

    const int t = threadIdx.x, lane = t & 31, wid = t >> 5;
    const int g = lane >> 2, tig = lane & 3;
    const int wm = wid & 3, wn = wid >> 2;
    const int bh = blockIdx.y, b = bh >> 3, h = bh & 7;
    const int q0 = blockIdx.x * 128;

    if (t < 128) {
        Rm[t] = rowM[(size_t)bh * S + q0 + t];
        Ri[t] = rowInv[(size_t)bh * S + q0 + t];
    }
    __syncthreads();

    float acc[2][4][4] = {};

    for (int kc = 0; kc < S; kc += 64) {
        // logits tile -> p, write back + stage
#pragma unroll
        for (int i = t; i < 2048; i += 256) {
            const int row = i >> 4, c4 = (i & 15) * 4;
            float* gp = &att[((size_t)bh * S + q0 + row) * S + kc + c4];
            float4 x = *reinterpret_cast<const float4*>(gp);
            const float M = Rm[row], Inv = Ri[row];
            float4 p;
            p.x = __expf(x.x - M) * Inv;
            p.y = __expf(x.y - M) * Inv;
            p.z = __expf(x.z - M) * Inv;
            p.w = __expf(x.w - M) * Inv;
            *reinterpret_cast<float4*>(gp) = p;
            *reinterpret_cast<float4*>(&As[row * AV_STRIDE + c4]) = p;
        }
        // V tile transposed + split: Vs[d][k]
#pragma unroll
        for (int i = t; i < 1024; i += 256) {
            const int k = i & 63, d4 = (i >> 6) * 4;
            float4 vv = *reinterpret_cast<const float4*>(
                &V[(size_t)(b * S + kc + k) * D + h * DK + d4]);
            uint4 hi, lo;
            split4(vv, hi, lo);
            Vhi[(d4 + 0) * AV_STRIDE + k] = hi.x; Vlo[(d4 + 0) * AV_STRIDE + k] = lo.x;
            Vhi[(d4 + 1) * AV_STRIDE + k] = hi.y; Vlo[(d4 + 1) * AV_STRIDE + k] = lo.y;
            Vhi[(d4 + 2) * AV_STRIDE + k] = hi.z; Vlo[(d4 + 2) * AV_STRIDE + k] = lo.z;
            Vhi[(d4 + 3) * AV_STRIDE + k] = hi.w; Vlo[(d4 + 3) * AV_STRIDE + k] = lo.w;
        }
        __syncthreads();

#pragma unroll
        for (int ks = 0; ks < 8; ks++) {
            const int kk = ks * 8;
            uint32_t ahi[2][4], alo[2][4];
#pragma unroll
            for (int i = 0; i < 2; i++) {
                const int r0 = (wm * 32 + i * 16 + g) * AV_STRIDE;
                const int r1 = r0 + 8 * AV_STRIDE;
                split_tf32(As[r0 + kk + tig],     ahi[i][0], alo[i][0]);
                split_tf32(As[r1 + kk + tig],     ahi[i][1], alo[i][1]);
                split_tf32(As[r0 + kk + tig + 4], ahi[i][2], alo[i][2]);
                split_tf32(As[r1 + kk + tig + 4], ahi[i][3], alo[i][3]);
            }
#pragma unroll
            for (int j = 0; j < 4; j++) {
                const int nr = (wn * 32 + j * 8 + g) * AV_STRIDE;
                uint32_t bhi[2], blo[2];
                bhi[0] = Vhi[nr + kk + tig];     blo[0] = Vlo[nr + kk + tig];
                bhi[1] = Vhi[nr + kk + tig + 4]; blo[1] = Vlo[nr + kk + tig + 4];
#pragma unroll
                for (int i = 0; i < 2; i++) {
                    mma_tf32(acc[i][j], ahi[i], bhi);
                    mma_tf32(acc[i][j], alo[i], bhi);
                    mma_tf32(acc[i][j], ahi[i], blo);
                }
            }
        }
        __syncthreads();
    }

#pragma unroll
    for (int i = 0; i < 2; i++) {
        const int row0 = q0 + wm * 32 + i * 16 + g;
#pragma unroll
        for (int j = 0; j < 4; j++) {
            const int col = h * DK + wn * 32 + j * 8 + 2 * tig;
            float2 o;
            o.x = acc[i][j][0]; o.y = acc[i][j][1];
            *reinterpret_cast<float2*>(&C[(size_t)(b * S + row0) * D + col]) = o;
            o.x = acc[i][j][2]; o.y = acc[i][j][3];
            *reinterpret_cast<float2*>(&C[(size_t)(b * S + row0 + 8) * D + col]) = o;
        }
    }
}

// ---------------------------------------------------------------------------
extern "C" void kernel_launch(void* const* d_in, const int* in_sizes, int n_in,
                              void* d_out, int out_size)
{
    const float* query = (const float*)d_in[0];
    const float* key   = (const float*)d_in[1];
    const float* value = (const float*)d_in[2];
    const int*   mask  = (const int*)d_in[3];
    const float* isog  = (const float*)d_in[4];
    const float* Wq    = (const float*)d_in[5];
    const float* bq    = (const float*)d_in[6];
    const float* Wk    = (const float*)d_in[7];
    const float* bk    = (const float*)d_in[8];
    const float* Wv    = (const float*)d_in[9];
    const float* bv    = (const float*)d_in[10];
    const float* Wo    = (const float*)d_in[11];
    const float* bo    = (const float*)d_in[12];
    const float* Worg  = (const float*)d_in[13];
    const float* borg  = (const float*)d_in[14];

    float* out = (float*)d_out;

    float *qbuf, *kbuf, *vbuf, *cbuf, *pmax, *psum, *rowM, *rowInv;
    cudaGetSymbolAddress((void**)&qbuf, g_Q);
    cudaGetSymbolAddress((void**)&kbuf, g_K);
    cudaGetSymbolAddress((void**)&vbuf, g_V);
    cudaGetSymbolAddress((void**)&cbuf, g_C);
    cudaGetSymbolAddress((void**)&pmax, g_pmax);
    cudaGetSymbolAddress((void**)&psum, g_psum);
    cudaGetSymbolAddress((void**)&rowM, g_rowM);
    cudaGetSymbolAddress((void**)&rowInv, g_rowInv);

    const long long OUT_MAIN = (long long)B * S * D;
    const long long ATT_SZ   = (long long)B * H * S * S;
    float* att;
    if ((long long)out_size >= OUT_MAIN + ATT_SZ) {
        att = out + OUT_MAIN;
    } else {
        cudaGetSymbolAddress((void**)&att, g_att);
    }

    static bool attr_done = false;
    if (!attr_done) {
        cudaFuncSetAttribute(scores_mma, cudaFuncAttributeMaxDynamicSharedMemorySize, SMEM_SCORES);
        cudaFuncSetAttribute(av_mma, cudaFuncAttributeMaxDynamicSharedMemorySize, SMEM_AV);
        cudaFuncSetAttribute(gemm_mma, cudaFuncAttributeMaxDynamicSharedMemorySize, SMEM_GEMM);
        attr_done = true;
    }

    dim3 gg(4, 64);   // N/128 x M/128
    gemm_mma<<<gg, 256, SMEM_GEMM>>>(query, Wq, bq, qbuf);
    gemm_mma<<<gg, 256, SMEM_GEMM>>>(key,   Wk, bk, kbuf);
    gemm_mma<<<gg, 256, SMEM_GEMM>>>(value, Wv, bv, vbuf);

    dim3 gs(S / 128, S / 128, B * H);
    scores_mma<<<gs, 256, SMEM_SCORES>>>(qbuf, kbuf, mask, isog, Worg, borg, att, pmax, psum);

    reduce_rows<<<(B * H * S) / 8, 256>>>(pmax, psum, rowM, rowInv);

    dim3 ga(S / 128, B * H);
    av_mma<<<ga, 256, SMEM_AV>>>(att, vbuf, rowM, rowInv, cbuf);

    gemm_mma<<<gg, 256, SMEM_GEMM>>>(cbuf, Wo, bo, out);
}

// round 6
// speedup vs baseline: 1.2598x; 1.2598x over previous
#include <cuda_runtime.h>
#include <cstdint>

namespace {
constexpr int B = 4, S = 2048, D = 512, H = 8, DK = 64;
}

// Scratch (allocation-free rule: __device__ globals)
__device__ float g_Q[(size_t)B * S * D];
__device__ float g_K[(size_t)B * S * D];
__device__ float g_V[(size_t)B * S * D];
__device__ float g_C[(size_t)B * S * D];
__device__ float g_att[(size_t)B * H * S * S];
// Split-softmax partials
__device__ float g_pmax[(size_t)B * H * S * 64];
__device__ float g_psum[(size_t)B * H * S * 64];
__device__ float g_rowM[(size_t)B * H * S];
__device__ float g_rowInv[(size_t)B * H * S];

// ============================================================================
// bf16 split + MMA helpers (portable PTX — works on compute_103)
// ============================================================================
// Pack (x0, x1) -> bf16x2 hi (x0 low half), and residual bf16x2 lo.
__device__ __forceinline__ void split_bf16x2(float x0, float x1, uint32_t& hi, uint32_t& lo) {
    asm("cvt.rn.bf16x2.f32 %0, %1, %2;" : "=r"(hi) : "f"(x1), "f"(x0));
    const float h0 = __uint_as_float(hi << 16);
    const float h1 = __uint_as_float(hi & 0xFFFF0000u);
    asm("cvt.rn.bf16x2.f32 %0, %1, %2;" : "=r"(lo) : "f"(x1 - h1), "f"(x0 - h0));
}
// m16n8k16 bf16 MMA, f32 accumulate
__device__ __forceinline__ void mma_bf16(float c[4], const uint32_t a[4], const uint32_t b[2]) {
    asm volatile(
        "mma.sync.aligned.m16n8k16.row.col.f32.bf16.bf16.f32 "
        "{%0,%1,%2,%3}, {%4,%5,%6,%7}, {%8,%9}, {%0,%1,%2,%3};"
        : "+f"(c[0]), "+f"(c[1]), "+f"(c[2]), "+f"(c[3])
        : "r"(a[0]), "r"(a[1]), "r"(a[2]), "r"(a[3]), "r"(b[0]), "r"(b[1]));
}

// k-pair smem arrays: [row][KPS] uints (bf16x2 along k). K=64 -> 32 pairs.
namespace {
constexpr int KPS = 36;   // pair stride (padded; bank-conflict-free: row*36 ≡ row*4 mod 32)
}

// ============================================================================
// Projection GEMM (bf16 3-term): Y[M,512] = X @ W^T + bias, M = 8192
// CTA 128x128, 256 thr = 8 warps (2m x 4n), K-chunk 64.
// ============================================================================
namespace {
constexpr int GM_XHI = 0;
constexpr int GM_XLO = 128 * KPS;
constexpr int GM_WHI = 2 * 128 * KPS;
constexpr int GM_WLO = 3 * 128 * KPS;
constexpr int SMEM_GEMM = 4 * 128 * KPS * 4;     // 73,728 bytes
}

__global__ void __launch_bounds__(256) gemm_mma(
    const float* __restrict__ X, const float* __restrict__ W,
    const float* __restrict__ bias, float* __restrict__ Y)
{
    extern __shared__ uint32_t smu[];
    uint32_t* Xhi = smu + GM_XHI;
    uint32_t* Xlo = smu + GM_XLO;
    uint32_t* Whi = smu + GM_WHI;
    uint32_t* Wlo = smu + GM_WLO;

    const int t = threadIdx.x, lane = t & 31, wid = t >> 5;
    const int g = lane >> 2, tig = lane & 3;
    const int wm = wid & 1, wn = wid >> 1;
    const int m0 = blockIdx.y * 128, n0 = blockIdx.x * 128;

    float acc[4][4][4] = {};

    for (int kc = 0; kc < 512; kc += 64) {
#pragma unroll
        for (int i = t; i < 2048; i += 256) {
            const int row = i >> 4, c4 = (i & 15) * 4, p = c4 >> 1;
            float4 xv = *reinterpret_cast<const float4*>(&X[(size_t)(m0 + row) * 512 + kc + c4]);
            float4 wv = *reinterpret_cast<const float4*>(&W[(size_t)(n0 + row) * 512 + kc + c4]);
            uint2 h, l;
            split_bf16x2(xv.x, xv.y, h.x, l.x);
            split_bf16x2(xv.z, xv.w, h.y, l.y);
            *reinterpret_cast<uint2*>(&Xhi[row * KPS + p]) = h;
            *reinterpret_cast<uint2*>(&Xlo[row * KPS + p]) = l;
            split_bf16x2(wv.x, wv.y, h.x, l.x);
            split_bf16x2(wv.z, wv.w, h.y, l.y);
            *reinterpret_cast<uint2*>(&Whi[row * KPS + p]) = h;
            *reinterpret_cast<uint2*>(&Wlo[row * KPS + p]) = l;
        }
        __syncthreads();

#pragma unroll
        for (int ks = 0; ks < 4; ks++) {
            const int kk = ks * 8;
            uint32_t ahi[4][4], alo[4][4];
#pragma unroll
            for (int i = 0; i < 4; i++) {
                const int r0 = (wm * 64 + i * 16 + g) * KPS;
                const int r1 = r0 + 8 * KPS;
                ahi[i][0] = Xhi[r0 + kk + tig];     alo[i][0] = Xlo[r0 + kk + tig];
                ahi[i][1] = Xhi[r1 + kk + tig];     alo[i][1] = Xlo[r1 + kk + tig];
                ahi[i][2] = Xhi[r0 + kk + tig + 4]; alo[i][2] = Xlo[r0 + kk + tig + 4];
                ahi[i][3] = Xhi[r1 + kk + tig + 4]; alo[i][3] = Xlo[r1 + kk + tig + 4];
            }
#pragma unroll
            for (int j = 0; j < 4; j++) {
                const int nr = (wn * 32 + j * 8 + g) * KPS;
                uint32_t bhi[2], blo[2];
                bhi[0] = Whi[nr + kk + tig];     blo[0] = Wlo[nr + kk + tig];
                bhi[1] = Whi[nr + kk + tig + 4]; blo[1] = Wlo[nr + kk + tig + 4];
#pragma unroll
                for (int i = 0; i < 4; i++) {
                    mma_bf16(acc[i][j], ahi[i], bhi);
                    mma_bf16(acc[i][j], alo[i], bhi);
                    mma_bf16(acc[i][j], ahi[i], blo);
                }
            }
        }
        __syncthreads();
    }

#pragma unroll
    for (int i = 0; i < 4; i++) {
        const int row0 = m0 + wm * 64 + i * 16 + g;
#pragma unroll
        for (int j = 0; j < 4; j++) {
            const int col = n0 + wn * 32 + j * 8 + 2 * tig;
            const float b0 = __ldg(bias + col), b1 = __ldg(bias + col + 1);
            float2 o;
            o.x = acc[i][j][0] + b0; o.y = acc[i][j][1] + b1;
            *reinterpret_cast<float2*>(&Y[(size_t)row0 * 512 + col]) = o;
            o.x = acc[i][j][2] + b0; o.y = acc[i][j][3] + b1;
            *reinterpret_cast<float2*>(&Y[(size_t)(row0 + 8) * 512 + col]) = o;
        }
    }
}

// ============================================================================
// Scores (bf16 3-term): logits = (Q.K)/8 + organic, masked; emits softmax
// partials per (row, 32-col warp tile).
// ============================================================================
namespace {
constexpr int SC_QHI = 0;
constexpr int SC_QLO = 128 * KPS;
constexpr int SC_KHI = 2 * 128 * KPS;
constexpr int SC_KLO = 3 * 128 * KPS;
constexpr int SMEM_SCORES = 4 * 128 * KPS * 4;   // 73,728 bytes
}

__global__ void __launch_bounds__(256) scores_mma(
    const float* __restrict__ Q, const float* __restrict__ K,
    const int* __restrict__ mask, const float* __restrict__ is_org,
    const float* __restrict__ Worg, const float* __restrict__ borg,
    float* __restrict__ att, float* __restrict__ pmax, float* __restrict__ psum)
{
    extern __shared__ uint32_t smu[];
    uint32_t* Qhi = smu + SC_QHI;
    uint32_t* Qlo = smu + SC_QLO;
    uint32_t* Khi = smu + SC_KHI;
    uint32_t* Klo = smu + SC_KLO;

    const int t = threadIdx.x, lane = t & 31, wid = t >> 5;
    const int g = lane >> 2, tig = lane & 3;
    const int wm = wid & 1, wn = wid >> 1;
    const int bh = blockIdx.z, b = bh >> 3, h = bh & 7;
    const int q0 = blockIdx.y * 128, k0g = blockIdx.x * 128;

    const float* Qg = Q + ((size_t)(b * S + q0)) * D + h * DK;
    const float* Kg = K + ((size_t)(b * S + k0g)) * D + h * DK;

#pragma unroll
    for (int i = t; i < 2048; i += 256) {
        const int row = i >> 4, c4 = (i & 15) * 4, p = c4 >> 1;
        float4 qv = *reinterpret_cast<const float4*>(Qg + (size_t)row * D + c4);
        float4 kv = *reinterpret_cast<const float4*>(Kg + (size_t)row * D + c4);
        uint2 h2, l2;
        split_bf16x2(qv.x, qv.y, h2.x, l2.x);
        split_bf16x2(qv.z, qv.w, h2.y, l2.y);
        *reinterpret_cast<uint2*>(&Qhi[row * KPS + p]) = h2;
        *reinterpret_cast<uint2*>(&Qlo[row * KPS + p]) = l2;
        split_bf16x2(kv.x, kv.y, h2.x, l2.x);
        split_bf16x2(kv.z, kv.w, h2.y, l2.y);
        *reinterpret_cast<uint2*>(&Khi[row * KPS + p]) = h2;
        *reinterpret_cast<uint2*>(&Klo[row * KPS + p]) = l2;
    }
    __syncthreads();

    float acc[4][4][4] = {};

#pragma unroll
    for (int ks = 0; ks < 4; ks++) {
        const int kk = ks * 8;
        uint32_t ahi[4][4], alo[4][4];
#pragma unroll
        for (int i = 0; i < 4; i++) {
            const int r0 = (wm * 64 + i * 16 + g) * KPS;
            const int r1 = r0 + 8 * KPS;
            ahi[i][0] = Qhi[r0 + kk + tig];     alo[i][0] = Qlo[r0 + kk + tig];
            ahi[i][1] = Qhi[r1 + kk + tig];     alo[i][1] = Qlo[r1 + kk + tig];
            ahi[i][2] = Qhi[r0 + kk + tig + 4]; alo[i][2] = Qlo[r0 + kk + tig + 4];
            ahi[i][3] = Qhi[r1 + kk + tig + 4]; alo[i][3] = Qlo[r1 + kk + tig + 4];
        }
#pragma unroll
        for (int j = 0; j < 4; j++) {
            const int nr = (wn * 32 + j * 8 + g) * KPS;
            uint32_t bhi[2], blo[2];
            bhi[0] = Khi[nr + kk + tig];     blo[0] = Klo[nr + kk + tig];
            bhi[1] = Khi[nr + kk + tig + 4]; blo[1] = Klo[nr + kk + tig + 4];
#pragma unroll
            for (int i = 0; i < 4; i++) {
                mma_bf16(acc[i][j], ahi[i], bhi);
                mma_bf16(acc[i][j], alo[i], bhi);
                mma_bf16(acc[i][j], ahi[i], blo);
            }
        }
    }

    // Finalize logits: scale + organic + mask
    const float worg = __ldg(Worg + h), bog = __ldg(borg + h);
    float og[4][2];
#pragma unroll
    for (int i = 0; i < 4; i++) {
#pragma unroll
        for (int hh = 0; hh < 2; hh++) {
            const int row = q0 + wm * 64 + i * 16 + g + hh * 8;
            og[i][hh] = __ldg(is_org + b * S + row) * worg + bog;
        }
    }
    int2 mj[4];
#pragma unroll
    for (int j = 0; j < 4; j++) {
        const int col = k0g + wn * 32 + j * 8 + 2 * tig;
        mj[j] = *reinterpret_cast<const int2*>(mask + b * S + col);
    }
#pragma unroll
    for (int i = 0; i < 4; i++) {
#pragma unroll
        for (int j = 0; j < 4; j++) {
            float v;
            v = acc[i][j][0] * 0.125f + og[i][0]; acc[i][j][0] = mj[j].x ? v : -1e9f;
            v = acc[i][j][1] * 0.125f + og[i][0]; acc[i][j][1] = mj[j].y ? v : -1e9f;
            v = acc[i][j][2] * 0.125f + og[i][1]; acc[i][j][2] = mj[j].x ? v : -1e9f;
            v = acc[i][j][3] * 0.125f + og[i][1]; acc[i][j][3] = mj[j].y ? v : -1e9f;
        }
    }

    // Store logits
#pragma unroll
    for (int i = 0; i < 4; i++) {
        const int row0 = q0 + wm * 64 + i * 16 + g;
#pragma unroll
        for (int j = 0; j < 4; j++) {
            const int col = k0g + wn * 32 + j * 8 + 2 * tig;
            float2 o;
            o.x = acc[i][j][0]; o.y = acc[i][j][1];
            *reinterpret_cast<float2*>(&att[((size_t)bh * S + row0) * S + col]) = o;
            o.x = acc[i][j][2]; o.y = acc[i][j][3];
            *reinterpret_cast<float2*>(&att[((size_t)bh * S + row0 + 8) * S + col]) = o;
        }
    }

    // Softmax partials per (row, 32-col warp tile)
    const int kwarp = blockIdx.x * 4 + wn;
#pragma unroll
    for (int i = 0; i < 4; i++) {
#pragma unroll
        for (int hh = 0; hh < 2; hh++) {
            float m = -1e30f;
#pragma unroll
            for (int j = 0; j < 4; j++)
                m = fmaxf(m, fmaxf(acc[i][j][hh * 2], acc[i][j][hh * 2 + 1]));
            m = fmaxf(m, __shfl_xor_sync(0xffffffffu, m, 1));
            m = fmaxf(m, __shfl_xor_sync(0xffffffffu, m, 2));
            float s = 0.0f;
#pragma unroll
            for (int j = 0; j < 4; j++)
                s += __expf(acc[i][j][hh * 2] - m) + __expf(acc[i][j][hh * 2 + 1] - m);
            s += __shfl_xor_sync(0xffffffffu, s, 1);
            s += __shfl_xor_sync(0xffffffffu, s, 2);
            if (tig == 0) {
                const size_t prow = (size_t)bh * S + q0 + wm * 64 + i * 16 + g + hh * 8;
                pmax[prow * 64 + kwarp] = m;
                psum[prow * 64 + kwarp] = s;
            }
        }
    }
}

// ============================================================================
// Row-stat reduce: 64 partials/row -> (M, 1/sum). One warp per row.
// ============================================================================
__global__ void __launch_bounds__(256) reduce_rows(
    const float* __restrict__ pmax, const float* __restrict__ psum,
    float* __restrict__ rowM, float* __restrict__ rowInv)
{
    const int wid = threadIdx.x >> 5, lane = threadIdx.x & 31;
    const size_t row = (size_t)blockIdx.x * 8 + wid;
    const float m0 = pmax[row * 64 + lane];
    const float m1 = pmax[row * 64 + lane + 32];
    float m = fmaxf(m0, m1);
#pragma unroll
    for (int o = 16; o; o >>= 1) m = fmaxf(m, __shfl_xor_sync(0xffffffffu, m, o));
    float s = psum[row * 64 + lane] * __expf(m0 - m)
            + psum[row * 64 + lane + 32] * __expf(m1 - m);
#pragma unroll
    for (int o = 16; o; o >>= 1) s += __shfl_xor_sync(0xffffffffu, s, o);
    if (lane == 0) {
        rowM[row] = m;
        rowInv[row] = 1.0f / s;
    }
}

// ============================================================================
// AV (bf16 3-term) with fused softmax normalization: reads logits, p=exp*inv,
// writes p back to att, accumulates p@V.
// ============================================================================
namespace {
constexpr int AV_AHI = 0;                       // uint [128][KPS]
constexpr int AV_ALO = 128 * KPS;
constexpr int AV_VHI = 2 * 128 * KPS;           // uint [64][KPS]
constexpr int AV_VLO = AV_VHI + 64 * KPS;
constexpr int AV_RM  = AV_VLO + 64 * KPS;       // float [128]
constexpr int AV_RI  = AV_RM + 128;
constexpr int SMEM_AV = (AV_RI + 128) * 4;      // 56,320 bytes
}

__global__ void __launch_bounds__(256) av_mma(
    float* __restrict__ att, const float* __restrict__ V,
    const float* __restrict__ rowM, const float* __restrict__ rowInv,
    float* __restrict__ C)
{
    extern __shared__ uint32_t smu[];
    uint32_t* Ahi = smu + AV_AHI;
    uint32_t* Alo = smu + AV_ALO;
    uint32_t* Vhi = smu + AV_VHI;
    uint32_t* Vlo = smu + AV_VLO;
    float*    Rm  = reinterpret_cast<float*>(smu + AV_RM);
    float*    Ri  = reinterpret_cast<float*>(smu + AV_RI);

    const int t = threadIdx.x, lane = t & 31, wid = t >> 5;
    const int g = lane >> 2, tig = lane & 3;
    const int wm = wid & 3, wn = wid >> 2;
    const int bh = blockIdx.y, b = bh >> 3, h = bh & 7;
    const int q0 = blockIdx.x * 128;

    if (t < 128) {
        Rm[t] = rowM[(size_t)bh * S + q0 + t];
        Ri[t] = rowInv[(size_t)bh * S + q0 + t];
    }
    __syncthreads();

    float acc[2][4][4] = {};

    for (int kc = 0; kc < S; kc += 64) {
        // logits -> p; write back; split to bf16 pairs
#pragma unroll
        for (int i = t; i < 2048; i += 256) {
            const int row = i >> 4, c4 = (i & 15) * 4, p4 = c4 >> 1;
            float* gp = &att[((size_t)bh * S + q0 + row) * S + kc + c4];
            float4 x = *reinterpret_cast<const float4*>(gp);
            const float M = Rm[row], Inv = Ri[row];
            float4 pp;
            pp.x = __expf(x.x - M) * Inv;
            pp.y = __expf(x.y - M) * Inv;
            pp.z = __expf(x.z - M) * Inv;
            pp.w = __expf(x.w - M) * Inv;
            *reinterpret_cast<float4*>(gp) = pp;
            uint2 h2, l2;
            split_bf16x2(pp.x, pp.y, h2.x, l2.x);
            split_bf16x2(pp.z, pp.w, h2.y, l2.y);
            *reinterpret_cast<uint2*>(&Ahi[row * KPS + p4]) = h2;
            *reinterpret_cast<uint2*>(&Alo[row * KPS + p4]) = l2;
        }
        // V tile: load two k-rows per thread, split/transpose into Vhi/Vlo[d][kp]
#pragma unroll
        for (int i = t; i < 512; i += 256) {
            const int dg = i & 15, kp = i >> 4;     // dg*4 = d base, kp = k pair
            const float* vp = &V[(size_t)(b * S + kc + 2 * kp) * D + h * DK + dg * 4];
            float4 va = *reinterpret_cast<const float4*>(vp);
            float4 vb = *reinterpret_cast<const float4*>(vp + D);
            uint32_t hi, lo;
            split_bf16x2(va.x, vb.x, hi, lo);
            Vhi[(dg * 4 + 0) * KPS + kp] = hi; Vlo[(dg * 4 + 0) * KPS + kp] = lo;
            split_bf16x2(va.y, vb.y, hi, lo);
            Vhi[(dg * 4 + 1) * KPS + kp] = hi; Vlo[(dg * 4 + 1) * KPS + kp] = lo;
            split_bf16x2(va.z, vb.z, hi, lo);
            Vhi[(dg * 4 + 2) * KPS + kp] = hi; Vlo[(dg * 4 + 2) * KPS + kp] = lo;
            split_bf16x2(va.w, vb.w, hi, lo);
            Vhi[(dg * 4 + 3) * KPS + kp] = hi; Vlo[(dg * 4 + 3) * KPS + kp] = lo;
        }
        __syncthreads();

#pragma unroll
        for (int ks = 0; ks < 4; ks++) {
            const int kk = ks * 8;
            uint32_t ahi[2][4], alo[2][4];
#pragma unroll
            for (int i = 0; i < 2; i++) {
                const int r0 = (wm * 32 + i * 16 + g) * KPS;
                const int r1 = r0 + 8 * KPS;
                ahi[i][0] = Ahi[r0 + kk + tig];     alo[i][0] = Alo[r0 + kk + tig];
                ahi[i][1] = Ahi[r1 + kk + tig];     alo[i][1] = Alo[r1 + kk + tig];
                ahi[i][2] = Ahi[r0 + kk + tig + 4]; alo[i][2] = Alo[r0 + kk + tig + 4];
                ahi[i][3] = Ahi[r1 + kk + tig + 4]; alo[i][3] = Alo[r1 + kk + tig + 4];
            }
#pragma unroll
            for (int j = 0; j < 4; j++) {
                const int nr = (wn * 32 + j * 8 + g) * KPS;
                uint32_t bhi[2], blo[2];
                bhi[0] = Vhi[nr + kk + tig];     blo[0] = Vlo[nr + kk + tig];
                bhi[1] = Vhi[nr + kk + tig + 4]; blo[1] = Vlo[nr + kk + tig + 4];
#pragma unroll
                for (int i = 0; i < 2; i++) {
                    mma_bf16(acc[i][j], ahi[i], bhi);
                    mma_bf16(acc[i][j], alo[i], bhi);
                    mma_bf16(acc[i][j], ahi[i], blo);
                }
            }
        }
        __syncthreads();
    }

#pragma unroll
    for (int i = 0; i < 2; i++) {
        const int row0 = q0 + wm * 32 + i * 16 + g;
#pragma unroll
        for (int j = 0; j < 4; j++) {
            const int col = h * DK + wn * 32 + j * 8 + 2 * tig;
            float2 o;
            o.x = acc[i][j][0]; o.y = acc[i][j][1];
            *reinterpret_cast<float2*>(&C[(size_t)(b * S + row0) * D + col]) = o;
            o.x = acc[i][j][2]; o.y = acc[i][j][3];
            *reinterpret_cast<float2*>(&C[(size_t)(b * S + row0 + 8) * D + col]) = o;
        }
    }
}

// ---------------------------------------------------------------------------
extern "C" void kernel_launch(void* const* d_in, const int* in_sizes, int n_in,
                              void* d_out, int out_size)
{
    const float* query = (const float*)d_in[0];
    const float* key   = (const float*)d_in[1];
    const float* value = (const float*)d_in[2];
    const int*   mask  = (const int*)d_in[3];
    const float* isog  = (const float*)d_in[4];
    const float* Wq    = (const float*)d_in[5];
    const float* bq    = (const float*)d_in[6];
    const float* Wk    = (const float*)d_in[7];
    const float* bk    = (const float*)d_in[8];
    const float* Wv    = (const float*)d_in[9];
    const float* bv    = (const float*)d_in[10];
    const float* Wo    = (const float*)d_in[11];
    const float* bo    = (const float*)d_in[12];
    const float* Worg  = (const float*)d_in[13];
    const float* borg  = (const float*)d_in[14];

    float* out = (float*)d_out;

    float *qbuf, *kbuf, *vbuf, *cbuf, *pmax, *psum, *rowM, *rowInv;
    cudaGetSymbolAddress((void**)&qbuf, g_Q);
    cudaGetSymbolAddress((void**)&kbuf, g_K);
    cudaGetSymbolAddress((void**)&vbuf, g_V);
    cudaGetSymbolAddress((void**)&cbuf, g_C);
    cudaGetSymbolAddress((void**)&pmax, g_pmax);
    cudaGetSymbolAddress((void**)&psum, g_psum);
    cudaGetSymbolAddress((void**)&rowM, g_rowM);
    cudaGetSymbolAddress((void**)&rowInv, g_rowInv);

    const long long OUT_MAIN = (long long)B * S * D;
    const long long ATT_SZ   = (long long)B * H * S * S;
    float* att;
    if ((long long)out_size >= OUT_MAIN + ATT_SZ) {
        att = out + OUT_MAIN;
    } else {
        cudaGetSymbolAddress((void**)&att, g_att);
    }

    static bool attr_done = false;
    if (!attr_done) {
        cudaFuncSetAttribute(scores_mma, cudaFuncAttributeMaxDynamicSharedMemorySize, SMEM_SCORES);
        cudaFuncSetAttribute(av_mma, cudaFuncAttributeMaxDynamicSharedMemorySize, SMEM_AV);
        cudaFuncSetAttribute(gemm_mma, cudaFuncAttributeMaxDynamicSharedMemorySize, SMEM_GEMM);
        attr_done = true;
    }

    dim3 gg(4, 64);
    gemm_mma<<<gg, 256, SMEM_GEMM>>>(query, Wq, bq, qbuf);
    gemm_mma<<<gg, 256, SMEM_GEMM>>>(key,   Wk, bk, kbuf);
    gemm_mma<<<gg, 256, SMEM_GEMM>>>(value, Wv, bv, vbuf);

    dim3 gs(S / 128, S / 128, B * H);
    scores_mma<<<gs, 256, SMEM_SCORES>>>(qbuf, kbuf, mask, isog, Worg, borg, att, pmax, psum);

    reduce_rows<<<(B * H * S) / 8, 256>>>(pmax, psum, rowM, rowInv);

    dim3 ga(S / 128, B * H);
    av_mma<<<ga, 256, SMEM_AV>>>(att, vbuf, rowM, rowInv, cbuf);

    gemm_mma<<<gg, 256, SMEM_GEMM>>>(cbuf, Wo, bo, out);
}

// round 7
// speedup vs baseline: 1.3590x; 1.0788x over previous
#include <cuda_runtime.h>
#include <cstdint>

namespace {
constexpr int B = 4, S = 2048, D = 512, H = 8, DK = 64;
}

// Scratch (allocation-free rule: __device__ globals)
__device__ float g_Q[(size_t)B * S * D];
__device__ float g_K[(size_t)B * S * D];
__device__ float g_V[(size_t)B * S * D];
__device__ float g_C[(size_t)B * S * D];
__device__ float g_att[(size_t)B * H * S * S];
// Split-softmax partials
__device__ float g_pmax[(size_t)B * H * S * 64];
__device__ float g_psum[(size_t)B * H * S * 64];
__device__ float g_rowM[(size_t)B * H * S];
__device__ float g_rowInv[(size_t)B * H * S];

// ============================================================================
// bf16 split + MMA helpers (portable PTX — works on compute_103)
// ============================================================================
__device__ __forceinline__ void split_bf16x2(float x0, float x1, uint32_t& hi, uint32_t& lo) {
    asm("cvt.rn.bf16x2.f32 %0, %1, %2;" : "=r"(hi) : "f"(x1), "f"(x0));
    const float h0 = __uint_as_float(hi << 16);
    const float h1 = __uint_as_float(hi & 0xFFFF0000u);
    asm("cvt.rn.bf16x2.f32 %0, %1, %2;" : "=r"(lo) : "f"(x1 - h1), "f"(x0 - h0));
}
__device__ __forceinline__ void mma_bf16(float c[4], const uint32_t a[4], const uint32_t b[2]) {
    asm volatile(
        "mma.sync.aligned.m16n8k16.row.col.f32.bf16.bf16.f32 "
        "{%0,%1,%2,%3}, {%4,%5,%6,%7}, {%8,%9}, {%0,%1,%2,%3};"
        : "+f"(c[0]), "+f"(c[1]), "+f"(c[2]), "+f"(c[3])
        : "r"(a[0]), "r"(a[1]), "r"(a[2]), "r"(a[3]), "r"(b[0]), "r"(b[1]));
}

namespace {
constexpr int KPS = 36;   // bf16x2-pair stride (padded)
}

// ============================================================================
// Projection GEMM (bf16 3-term): Y[M,512] = X @ W^T + bias, M = 8192
// ============================================================================
namespace {
constexpr int GM_XHI = 0;
constexpr int GM_XLO = 128 * KPS;
constexpr int GM_WHI = 2 * 128 * KPS;
constexpr int GM_WLO = 3 * 128 * KPS;
constexpr int SMEM_GEMM = 4 * 128 * KPS * 4;     // 73,728 bytes
}

__global__ void __launch_bounds__(256, 2) gemm_mma(
    const float* __restrict__ X, const float* __restrict__ W,
    const float* __restrict__ bias, float* __restrict__ Y)
{
    extern __shared__ uint32_t smu[];
    uint32_t* Xhi = smu + GM_XHI;
    uint32_t* Xlo = smu + GM_XLO;
    uint32_t* Whi = smu + GM_WHI;
    uint32_t* Wlo = smu + GM_WLO;

    const int t = threadIdx.x, lane = t & 31, wid = t >> 5;
    const int g = lane >> 2, tig = lane & 3;
    const int wm = wid & 1, wn = wid >> 1;
    const int m0 = blockIdx.y * 128, n0 = blockIdx.x * 128;

    float acc[4][4][4] = {};

    for (int kc = 0; kc < 512; kc += 64) {
#pragma unroll
        for (int i = t; i < 2048; i += 256) {
            const int row = i >> 4, c4 = (i & 15) * 4, p = c4 >> 1;
            float4 xv = *reinterpret_cast<const float4*>(&X[(size_t)(m0 + row) * 512 + kc + c4]);
            float4 wv = *reinterpret_cast<const float4*>(&W[(size_t)(n0 + row) * 512 + kc + c4]);
            uint2 h, l;
            split_bf16x2(xv.x, xv.y, h.x, l.x);
            split_bf16x2(xv.z, xv.w, h.y, l.y);
            *reinterpret_cast<uint2*>(&Xhi[row * KPS + p]) = h;
            *reinterpret_cast<uint2*>(&Xlo[row * KPS + p]) = l;
            split_bf16x2(wv.x, wv.y, h.x, l.x);
            split_bf16x2(wv.z, wv.w, h.y, l.y);
            *reinterpret_cast<uint2*>(&Whi[row * KPS + p]) = h;
            *reinterpret_cast<uint2*>(&Wlo[row * KPS + p]) = l;
        }
        __syncthreads();

#pragma unroll
        for (int ks = 0; ks < 4; ks++) {
            const int kk = ks * 8;
            uint32_t ahi[4][4], alo[4][4];
#pragma unroll
            for (int i = 0; i < 4; i++) {
                const int r0 = (wm * 64 + i * 16 + g) * KPS;
                const int r1 = r0 + 8 * KPS;
                ahi[i][0] = Xhi[r0 + kk + tig];     alo[i][0] = Xlo[r0 + kk + tig];
                ahi[i][1] = Xhi[r1 + kk + tig];     alo[i][1] = Xlo[r1 + kk + tig];
                ahi[i][2] = Xhi[r0 + kk + tig + 4]; alo[i][2] = Xlo[r0 + kk + tig + 4];
                ahi[i][3] = Xhi[r1 + kk + tig + 4]; alo[i][3] = Xlo[r1 + kk + tig + 4];
            }
#pragma unroll
            for (int j = 0; j < 4; j++) {
                const int nr = (wn * 32 + j * 8 + g) * KPS;
                uint32_t bhi[2], blo[2];
                bhi[0] = Whi[nr + kk + tig];     blo[0] = Wlo[nr + kk + tig];
                bhi[1] = Whi[nr + kk + tig + 4]; blo[1] = Wlo[nr + kk + tig + 4];
#pragma unroll
                for (int i = 0; i < 4; i++) {
                    mma_bf16(acc[i][j], ahi[i], bhi);
                    mma_bf16(acc[i][j], alo[i], bhi);
                    mma_bf16(acc[i][j], ahi[i], blo);
                }
            }
        }
        __syncthreads();
    }

#pragma unroll
    for (int i = 0; i < 4; i++) {
        const int row0 = m0 + wm * 64 + i * 16 + g;
#pragma unroll
        for (int j = 0; j < 4; j++) {
            const int col = n0 + wn * 32 + j * 8 + 2 * tig;
            const float b0 = __ldg(bias + col), b1 = __ldg(bias + col + 1);
            float2 o;
            o.x = acc[i][j][0] + b0; o.y = acc[i][j][1] + b1;
            *reinterpret_cast<float2*>(&Y[(size_t)row0 * 512 + col]) = o;
            o.x = acc[i][j][2] + b0; o.y = acc[i][j][3] + b1;
            *reinterpret_cast<float2*>(&Y[(size_t)(row0 + 8) * 512 + col]) = o;
        }
    }
}

// ============================================================================
// Scores (bf16 3-term) + split-softmax partials
// ============================================================================
namespace {
constexpr int SC_QHI = 0;
constexpr int SC_QLO = 128 * KPS;
constexpr int SC_KHI = 2 * 128 * KPS;
constexpr int SC_KLO = 3 * 128 * KPS;
constexpr int SMEM_SCORES = 4 * 128 * KPS * 4;   // 73,728 bytes
}

__global__ void __launch_bounds__(256, 2) scores_mma(
    const float* __restrict__ Q, const float* __restrict__ K,
    const int* __restrict__ mask, const float* __restrict__ is_org,
    const float* __restrict__ Worg, const float* __restrict__ borg,
    float* __restrict__ att, float* __restrict__ pmax, float* __restrict__ psum)
{
    extern __shared__ uint32_t smu[];
    uint32_t* Qhi = smu + SC_QHI;
    uint32_t* Qlo = smu + SC_QLO;
    uint32_t* Khi = smu + SC_KHI;
    uint32_t* Klo = smu + SC_KLO;

    const int t = threadIdx.x, lane = t & 31, wid = t >> 5;
    const int g = lane >> 2, tig = lane & 3;
    const int wm = wid & 1, wn = wid >> 1;
    const int bh = blockIdx.z, b = bh >> 3, h = bh & 7;
    const int q0 = blockIdx.y * 128, k0g = blockIdx.x * 128;

    const float* Qg = Q + ((size_t)(b * S + q0)) * D + h * DK;
    const float* Kg = K + ((size_t)(b * S + k0g)) * D + h * DK;

#pragma unroll
    for (int i = t; i < 2048; i += 256) {
        const int row = i >> 4, c4 = (i & 15) * 4, p = c4 >> 1;
        float4 qv = *reinterpret_cast<const float4*>(Qg + (size_t)row * D + c4);
        float4 kv = *reinterpret_cast<const float4*>(Kg + (size_t)row * D + c4);
        uint2 h2, l2;
        split_bf16x2(qv.x, qv.y, h2.x, l2.x);
        split_bf16x2(qv.z, qv.w, h2.y, l2.y);
        *reinterpret_cast<uint2*>(&Qhi[row * KPS + p]) = h2;
        *reinterpret_cast<uint2*>(&Qlo[row * KPS + p]) = l2;
        split_bf16x2(kv.x, kv.y, h2.x, l2.x);
        split_bf16x2(kv.z, kv.w, h2.y, l2.y);
        *reinterpret_cast<uint2*>(&Khi[row * KPS + p]) = h2;
        *reinterpret_cast<uint2*>(&Klo[row * KPS + p]) = l2;
    }
    __syncthreads();

    float acc[4][4][4] = {};

#pragma unroll
    for (int ks = 0; ks < 4; ks++) {
        const int kk = ks * 8;
        uint32_t ahi[4][4], alo[4][4];
#pragma unroll
        for (int i = 0; i < 4; i++) {
            const int r0 = (wm * 64 + i * 16 + g) * KPS;
            const int r1 = r0 + 8 * KPS;
            ahi[i][0] = Qhi[r0 + kk + tig];     alo[i][0] = Qlo[r0 + kk + tig];
            ahi[i][1] = Qhi[r1 + kk + tig];     alo[i][1] = Qlo[r1 + kk + tig];
            ahi[i][2] = Qhi[r0 + kk + tig + 4]; alo[i][2] = Qlo[r0 + kk + tig + 4];
            ahi[i][3] = Qhi[r1 + kk + tig + 4]; alo[i][3] = Qlo[r1 + kk + tig + 4];
        }
#pragma unroll
        for (int j = 0; j < 4; j++) {
            const int nr = (wn * 32 + j * 8 + g) * KPS;
            uint32_t bhi[2], blo[2];
            bhi[0] = Khi[nr + kk + tig];     blo[0] = Klo[nr + kk + tig];
            bhi[1] = Khi[nr + kk + tig + 4]; blo[1] = Klo[nr + kk + tig + 4];
#pragma unroll
            for (int i = 0; i < 4; i++) {
                mma_bf16(acc[i][j], ahi[i], bhi);
                mma_bf16(acc[i][j], alo[i], bhi);
                mma_bf16(acc[i][j], ahi[i], blo);
            }
        }
    }

    // Finalize logits: scale + organic + mask
    const float worg = __ldg(Worg + h), bog = __ldg(borg + h);
    float og[4][2];
#pragma unroll
    for (int i = 0; i < 4; i++) {
#pragma unroll
        for (int hh = 0; hh < 2; hh++) {
            const int row = q0 + wm * 64 + i * 16 + g + hh * 8;
            og[i][hh] = __ldg(is_org + b * S + row) * worg + bog;
        }
    }
    int2 mj[4];
#pragma unroll
    for (int j = 0; j < 4; j++) {
        const int col = k0g + wn * 32 + j * 8 + 2 * tig;
        mj[j] = *reinterpret_cast<const int2*>(mask + b * S + col);
    }
#pragma unroll
    for (int i = 0; i < 4; i++) {
#pragma unroll
        for (int j = 0; j < 4; j++) {
            float v;
            v = acc[i][j][0] * 0.125f + og[i][0]; acc[i][j][0] = mj[j].x ? v : -1e9f;
            v = acc[i][j][1] * 0.125f + og[i][0]; acc[i][j][1] = mj[j].y ? v : -1e9f;
            v = acc[i][j][2] * 0.125f + og[i][1]; acc[i][j][2] = mj[j].x ? v : -1e9f;
            v = acc[i][j][3] * 0.125f + og[i][1]; acc[i][j][3] = mj[j].y ? v : -1e9f;
        }
    }

    // Store logits
#pragma unroll
    for (int i = 0; i < 4; i++) {
        const int row0 = q0 + wm * 64 + i * 16 + g;
#pragma unroll
        for (int j = 0; j < 4; j++) {
            const int col = k0g + wn * 32 + j * 8 + 2 * tig;
            float2 o;
            o.x = acc[i][j][0]; o.y = acc[i][j][1];
            *reinterpret_cast<float2*>(&att[((size_t)bh * S + row0) * S + col]) = o;
            o.x = acc[i][j][2]; o.y = acc[i][j][3];
            *reinterpret_cast<float2*>(&att[((size_t)bh * S + row0 + 8) * S + col]) = o;
        }
    }

    // Softmax partials per (row, 32-col warp tile)
    const int kwarp = blockIdx.x * 4 + wn;
#pragma unroll
    for (int i = 0; i < 4; i++) {
#pragma unroll
        for (int hh = 0; hh < 2; hh++) {
            float m = -1e30f;
#pragma unroll
            for (int j = 0; j < 4; j++)
                m = fmaxf(m, fmaxf(acc[i][j][hh * 2], acc[i][j][hh * 2 + 1]));
            m = fmaxf(m, __shfl_xor_sync(0xffffffffu, m, 1));
            m = fmaxf(m, __shfl_xor_sync(0xffffffffu, m, 2));
            float s = 0.0f;
#pragma unroll
            for (int j = 0; j < 4; j++)
                s += __expf(acc[i][j][hh * 2] - m) + __expf(acc[i][j][hh * 2 + 1] - m);
            s += __shfl_xor_sync(0xffffffffu, s, 1);
            s += __shfl_xor_sync(0xffffffffu, s, 2);
            if (tig == 0) {
                const size_t prow = (size_t)bh * S + q0 + wm * 64 + i * 16 + g + hh * 8;
                pmax[prow * 64 + kwarp] = m;
                psum[prow * 64 + kwarp] = s;
            }
        }
    }
}

// ============================================================================
// Row-stat reduce: 64 partials/row -> (M, 1/sum). One warp per row.
// ============================================================================
__global__ void __launch_bounds__(256) reduce_rows(
    const float* __restrict__ pmax, const float* __restrict__ psum,
    float* __restrict__ rowM, float* __restrict__ rowInv)
{
    const int wid = threadIdx.x >> 5, lane = threadIdx.x & 31;
    const size_t row = (size_t)blockIdx.x * 8 + wid;
    const float m0 = pmax[row * 64 + lane];
    const float m1 = pmax[row * 64 + lane + 32];
    float m = fmaxf(m0, m1);
#pragma unroll
    for (int o = 16; o; o >>= 1) m = fmaxf(m, __shfl_xor_sync(0xffffffffu, m, o));
    float s = psum[row * 64 + lane] * __expf(m0 - m)
            + psum[row * 64 + lane + 32] * __expf(m1 - m);
#pragma unroll
    for (int o = 16; o; o >>= 1) s += __shfl_xor_sync(0xffffffffu, s, o);
    if (lane == 0) {
        rowM[row] = m;
        rowInv[row] = 1.0f / s;
    }
}

// ============================================================================
// AV (bf16 3-term) with fused softmax normalization
// ============================================================================
namespace {
constexpr int AV_AHI = 0;
constexpr int AV_ALO = 128 * KPS;
constexpr int AV_VHI = 2 * 128 * KPS;
constexpr int AV_VLO = AV_VHI + 64 * KPS;
constexpr int AV_RM  = AV_VLO + 64 * KPS;
constexpr int AV_RI  = AV_RM + 128;
constexpr int SMEM_AV = (AV_RI + 128) * 4;      // 56,320 bytes
}

__global__ void __launch_bounds__(256, 2) av_mma(
    float* __restrict__ att, const float* __restrict__ V,
    const float* __restrict__ rowM, const float* __restrict__ rowInv,
    float* __restrict__ C)
{
    extern __shared__ uint32_t smu[];
    uint32_t* Ahi = smu + AV_AHI;
    uint32_t* Alo = smu + AV_ALO;
    uint32_t* Vhi = smu + AV_VHI;
    uint32_t* Vlo = smu + AV_VLO;
    float*    Rm  = reinterpret_cast<float*>(smu + AV_RM);
    float*    Ri  = reinterpret_cast<float*>(smu + AV_RI);

    const int t = threadIdx.x, lane = t & 31, wid = t >> 5;
    const int g = lane >> 2, tig = lane & 3;
    const int wm = wid & 3, wn = wid >> 2;
    const int bh = blockIdx.y, b = bh >> 3, h = bh & 7;
    const int q0 = blockIdx.x * 128;

    if (t < 128) {
        Rm[t] = rowM[(size_t)bh * S + q0 + t];
        Ri[t] = rowInv[(size_t)bh * S + q0 + t];
    }
    __syncthreads();

    float acc[2][4][4] = {};

    for (int kc = 0; kc < S; kc += 64) {
#pragma unroll
        for (int i = t; i < 2048; i += 256) {
            const int row = i >> 4, c4 = (i & 15) * 4, p4 = c4 >> 1;
            float* gp = &att[((size_t)bh * S + q0 + row) * S + kc + c4];
            float4 x = *reinterpret_cast<const float4*>(gp);
            const float M = Rm[row], Inv = Ri[row];
            float4 pp;
            pp.x = __expf(x.x - M) * Inv;
            pp.y = __expf(x.y - M) * Inv;
            pp.z = __expf(x.z - M) * Inv;
            pp.w = __expf(x.w - M) * Inv;
            *reinterpret_cast<float4*>(gp) = pp;
            uint2 h2, l2;
            split_bf16x2(pp.x, pp.y, h2.x, l2.x);
            split_bf16x2(pp.z, pp.w, h2.y, l2.y);
            *reinterpret_cast<uint2*>(&Ahi[row * KPS + p4]) = h2;
            *reinterpret_cast<uint2*>(&Alo[row * KPS + p4]) = l2;
        }
#pragma unroll
        for (int i = t; i < 512; i += 256) {
            const int dg = i & 15, kp = i >> 4;
            const float* vp = &V[(size_t)(b * S + kc + 2 * kp) * D + h * DK + dg * 4];
            float4 va = *reinterpret_cast<const float4*>(vp);
            float4 vb = *reinterpret_cast<const float4*>(vp + D);
            uint32_t hi, lo;
            split_bf16x2(va.x, vb.x, hi, lo);
            Vhi[(dg * 4 + 0) * KPS + kp] = hi; Vlo[(dg * 4 + 0) * KPS + kp] = lo;
            split_bf16x2(va.y, vb.y, hi, lo);
            Vhi[(dg * 4 + 1) * KPS + kp] = hi; Vlo[(dg * 4 + 1) * KPS + kp] = lo;
            split_bf16x2(va.z, vb.z, hi, lo);
            Vhi[(dg * 4 + 2) * KPS + kp] = hi; Vlo[(dg * 4 + 2) * KPS + kp] = lo;
            split_bf16x2(va.w, vb.w, hi, lo);
            Vhi[(dg * 4 + 3) * KPS + kp] = hi; Vlo[(dg * 4 + 3) * KPS + kp] = lo;
        }
        __syncthreads();

#pragma unroll
        for (int ks = 0; ks < 4; ks++) {
            const int kk = ks * 8;
            uint32_t ahi[2][4], alo[2][4];
#pragma unroll
            for (int i = 0; i < 2; i++) {
                const int r0 = (wm * 32 + i * 16 + g) * KPS;
                const int r1 = r0 + 8 * KPS;
                ahi[i][0] = Ahi[r0 + kk + tig];     alo[i][0] = Alo[r0 + kk + tig];
                ahi[i][1] = Ahi[r1 + kk + tig];     alo[i][1] = Alo[r1 + kk + tig];
                ahi[i][2] = Ahi[r0 + kk + tig + 4]; alo[i][2] = Alo[r0 + kk + tig + 4];
                ahi[i][3] = Ahi[r1 + kk + tig + 4]; alo[i][3] = Alo[r1 + kk + tig + 4];
            }
#pragma unroll
            for (int j = 0; j < 4; j++) {
                const int nr = (wn * 32 + j * 8 + g) * KPS;
                uint32_t bhi[2], blo[2];
                bhi[0] = Vhi[nr + kk + tig];     blo[0] = Vlo[nr + kk + tig];
                bhi[1] = Vhi[nr + kk + tig + 4]; blo[1] = Vlo[nr + kk + tig + 4];
#pragma unroll
                for (int i = 0; i < 2; i++) {
                    mma_bf16(acc[i][j], ahi[i], bhi);
                    mma_bf16(acc[i][j], alo[i], bhi);
                    mma_bf16(acc[i][j], ahi[i], blo);
                }
            }
        }
        __syncthreads();
    }

#pragma unroll
    for (int i = 0; i < 2; i++) {
        const int row0 = q0 + wm * 32 + i * 16 + g;
#pragma unroll
        for (int j = 0; j < 4; j++) {
            const int col = h * DK + wn * 32 + j * 8 + 2 * tig;
            float2 o;
            o.x = acc[i][j][0]; o.y = acc[i][j][1];
            *reinterpret_cast<float2*>(&C[(size_t)(b * S + row0) * D + col]) = o;
            o.x = acc[i][j][2]; o.y = acc[i][j][3];
            *reinterpret_cast<float2*>(&C[(size_t)(b * S + row0 + 8) * D + col]) = o;
        }
    }
}

// ---------------------------------------------------------------------------
extern "C" void kernel_launch(void* const* d_in, const int* in_sizes, int n_in,
                              void* d_out, int out_size)
{
    const float* query = (const float*)d_in[0];
    const float* key   = (const float*)d_in[1];
    const float* value = (const float*)d_in[2];
    const int*   mask  = (const int*)d_in[3];
    const float* isog  = (const float*)d_in[4];
    const float* Wq    = (const float*)d_in[5];
    const float* bq    = (const float*)d_in[6];
    const float* Wk    = (const float*)d_in[7];
    const float* bk    = (const float*)d_in[8];
    const float* Wv    = (const float*)d_in[9];
    const float* bv    = (const float*)d_in[10];
    const float* Wo    = (const float*)d_in[11];
    const float* bo    = (const float*)d_in[12];
    const float* Worg  = (const float*)d_in[13];
    const float* borg  = (const float*)d_in[14];

    float* out = (float*)d_out;

    float *qbuf, *kbuf, *vbuf, *cbuf, *pmax, *psum, *rowM, *rowInv;
    cudaGetSymbolAddress((void**)&qbuf, g_Q);
    cudaGetSymbolAddress((void**)&kbuf, g_K);
    cudaGetSymbolAddress((void**)&vbuf, g_V);
    cudaGetSymbolAddress((void**)&cbuf, g_C);
    cudaGetSymbolAddress((void**)&pmax, g_pmax);
    cudaGetSymbolAddress((void**)&psum, g_psum);
    cudaGetSymbolAddress((void**)&rowM, g_rowM);
    cudaGetSymbolAddress((void**)&rowInv, g_rowInv);

    const long long OUT_MAIN = (long long)B * S * D;
    const long long ATT_SZ   = (long long)B * H * S * S;
    float* att;
    if ((long long)out_size >= OUT_MAIN + ATT_SZ) {
        att = out + OUT_MAIN;
    } else {
        cudaGetSymbolAddress((void**)&att, g_att);
    }

    static bool attr_done = false;
    if (!attr_done) {
        cudaFuncSetAttribute(scores_mma, cudaFuncAttributeMaxDynamicSharedMemorySize, SMEM_SCORES);
        cudaFuncSetAttribute(av_mma, cudaFuncAttributeMaxDynamicSharedMemorySize, SMEM_AV);
        cudaFuncSetAttribute(gemm_mma, cudaFuncAttributeMaxDynamicSharedMemorySize, SMEM_GEMM);
        attr_done = true;
    }

    dim3 gg(4, 64);
    gemm_mma<<<gg, 256, SMEM_GEMM>>>(query, Wq, bq, qbuf);
    gemm_mma<<<gg, 256, SMEM_GEMM>>>(key,   Wk, bk, kbuf);
    gemm_mma<<<gg, 256, SMEM_GEMM>>>(value, Wv, bv, vbuf);

    dim3 gs(S / 128, S / 128, B * H);
    scores_mma<<<gs, 256, SMEM_SCORES>>>(qbuf, kbuf, mask, isog, Worg, borg, att, pmax, psum);

    reduce_rows<<<(B * H * S) / 8, 256>>>(pmax, psum, rowM, rowInv);

    dim3 ga(S / 128, B * H);
    av_mma<<<ga, 256, SMEM_AV>>>(att, vbuf, rowM, rowInv, cbuf);

    gemm_mma<<<gg, 256, SMEM_GEMM>>>(cbuf, Wo, bo, out);
}

// round 8
// speedup vs baseline: 1.4854x; 1.0930x over previous
#include <cuda_runtime.h>
#include <cstdint>

namespace {
constexpr int B = 4, S = 2048, D = 512, H = 8, DK = 64;
}

// Scratch (allocation-free rule: __device__ globals)
__device__ float g_Q[(size_t)B * S * D];
__device__ float g_K[(size_t)B * S * D];
__device__ float g_V[(size_t)B * S * D];
__device__ float g_C[(size_t)B * S * D];
__device__ float g_att[(size_t)B * H * S * S];
// Split-softmax partials
__device__ float g_pmax[(size_t)B * H * S * 64];
__device__ float g_psum[(size_t)B * H * S * 64];
__device__ float g_rowM[(size_t)B * H * S];
__device__ float g_rowInv[(size_t)B * H * S];

// ============================================================================
// bf16 split, MMA, ldmatrix helpers (portable PTX — works on compute_103)
// ============================================================================
__device__ __forceinline__ void split_bf16x2(float x0, float x1, uint32_t& hi, uint32_t& lo) {
    asm("cvt.rn.bf16x2.f32 %0, %1, %2;" : "=r"(hi) : "f"(x1), "f"(x0));
    const float h0 = __uint_as_float(hi << 16);
    const float h1 = __uint_as_float(hi & 0xFFFF0000u);
    asm("cvt.rn.bf16x2.f32 %0, %1, %2;" : "=r"(lo) : "f"(x1 - h1), "f"(x0 - h0));
}
__device__ __forceinline__ void mma_bf16(float c[4], const uint32_t a[4], const uint32_t b[2]) {
    asm volatile(
        "mma.sync.aligned.m16n8k16.row.col.f32.bf16.bf16.f32 "
        "{%0,%1,%2,%3}, {%4,%5,%6,%7}, {%8,%9}, {%0,%1,%2,%3};"
        : "+f"(c[0]), "+f"(c[1]), "+f"(c[2]), "+f"(c[3])
        : "r"(a[0]), "r"(a[1]), "r"(a[2]), "r"(a[3]), "r"(b[0]), "r"(b[1]));
}
__device__ __forceinline__ void ldmx4(uint32_t r[4], uint32_t addr) {
    asm volatile("ldmatrix.sync.aligned.m8n8.x4.shared.b16 {%0,%1,%2,%3}, [%4];"
                 : "=r"(r[0]), "=r"(r[1]), "=r"(r[2]), "=r"(r[3]) : "r"(addr));
}
__device__ __forceinline__ void ldmx2(uint32_t r[2], uint32_t addr) {
    asm volatile("ldmatrix.sync.aligned.m8n8.x2.shared.b16 {%0,%1}, [%2];"
                 : "=r"(r[0]), "=r"(r[1]) : "r"(addr));
}
__device__ __forceinline__ uint32_t smaddr(const void* p) {
    return (uint32_t)__cvta_generic_to_shared(p);
}

namespace {
constexpr int KPS = 36;   // bf16x2-pair stride (padded; row stride 144B -> conflict-free)
}

// ============================================================================
// Projection GEMM (bf16 3-term): Y[M,512] = X @ W^T + bias, M = 8192
// CTA 128x128, 8 warps (2m x 4n), K-chunk 64.
// ============================================================================
namespace {
constexpr int GM_XHI = 0;
constexpr int GM_XLO = 128 * KPS;
constexpr int GM_WHI = 2 * 128 * KPS;
constexpr int GM_WLO = 3 * 128 * KPS;
constexpr int SMEM_GEMM = 4 * 128 * KPS * 4;     // 73,728 bytes
}

__global__ void __launch_bounds__(256, 2) gemm_mma(
    const float* __restrict__ X, const float* __restrict__ W,
    const float* __restrict__ bias, float* __restrict__ Y)
{
    extern __shared__ uint32_t smu[];
    uint32_t* Xhi = smu + GM_XHI;
    uint32_t* Xlo = smu + GM_XLO;
    uint32_t* Whi = smu + GM_WHI;
    uint32_t* Wlo = smu + GM_WLO;

    const int t = threadIdx.x, lane = t & 31, wid = t >> 5;
    const int g = lane >> 2, tig = lane & 3;
    const int wm = wid & 1, wn = wid >> 1;
    const int m0 = blockIdx.y * 128, n0 = blockIdx.x * 128;

    // ldmatrix per-lane base addresses
    const int am = lane >> 3, arm = lane & 7;           // A: matrix idx, row-in-matrix
    const int bmat = (lane >> 3) & 1, brm = lane & 7;   // B: matrix idx, row
    uint32_t aHi[4], aLo[4], bHi[4], bLo[4];
#pragma unroll
    for (int i = 0; i < 4; i++) {
        const int row = wm * 64 + i * 16 + (am & 1) * 8 + arm;
        const uint32_t off = (uint32_t)(row * KPS + (am >> 1) * 4) * 4u;
        aHi[i] = smaddr(Xhi) + off;
        aLo[i] = smaddr(Xlo) + off;
    }
#pragma unroll
    for (int j = 0; j < 4; j++) {
        const int row = wn * 32 + j * 8 + brm;
        const uint32_t off = (uint32_t)(row * KPS + bmat * 4) * 4u;
        bHi[j] = smaddr(Whi) + off;
        bLo[j] = smaddr(Wlo) + off;
    }

    float acc[4][4][4] = {};

    for (int kc = 0; kc < 512; kc += 64) {
#pragma unroll
        for (int i = t; i < 2048; i += 256) {
            const int row = i >> 4, c4 = (i & 15) * 4, p = c4 >> 1;
            float4 xv = *reinterpret_cast<const float4*>(&X[(size_t)(m0 + row) * 512 + kc + c4]);
            float4 wv = *reinterpret_cast<const float4*>(&W[(size_t)(n0 + row) * 512 + kc + c4]);
            uint2 h, l;
            split_bf16x2(xv.x, xv.y, h.x, l.x);
            split_bf16x2(xv.z, xv.w, h.y, l.y);
            *reinterpret_cast<uint2*>(&Xhi[row * KPS + p]) = h;
            *reinterpret_cast<uint2*>(&Xlo[row * KPS + p]) = l;
            split_bf16x2(wv.x, wv.y, h.x, l.x);
            split_bf16x2(wv.z, wv.w, h.y, l.y);
            *reinterpret_cast<uint2*>(&Whi[row * KPS + p]) = h;
            *reinterpret_cast<uint2*>(&Wlo[row * KPS + p]) = l;
        }
        __syncthreads();

#pragma unroll
        for (int ks = 0; ks < 4; ks++) {
            const uint32_t ko = ks * 32u;   // 8 pairs * 4 bytes
            uint32_t ahi[4][4], alo[4][4];
#pragma unroll
            for (int i = 0; i < 4; i++) {
                ldmx4(ahi[i], aHi[i] + ko);
                ldmx4(alo[i], aLo[i] + ko);
            }
#pragma unroll
            for (int j = 0; j < 4; j++) {
                uint32_t bhi[2], blo[2];
                ldmx2(bhi, bHi[j] + ko);
                ldmx2(blo, bLo[j] + ko);
#pragma unroll
                for (int i = 0; i < 4; i++) {
                    mma_bf16(acc[i][j], ahi[i], bhi);
                    mma_bf16(acc[i][j], alo[i], bhi);
                    mma_bf16(acc[i][j], ahi[i], blo);
                }
            }
        }
        __syncthreads();
    }

#pragma unroll
    for (int i = 0; i < 4; i++) {
        const int row0 = m0 + wm * 64 + i * 16 + g;
#pragma unroll
        for (int j = 0; j < 4; j++) {
            const int col = n0 + wn * 32 + j * 8 + 2 * tig;
            const float b0 = __ldg(bias + col), b1 = __ldg(bias + col + 1);
            float2 o;
            o.x = acc[i][j][0] + b0; o.y = acc[i][j][1] + b1;
            *reinterpret_cast<float2*>(&Y[(size_t)row0 * 512 + col]) = o;
            o.x = acc[i][j][2] + b0; o.y = acc[i][j][3] + b1;
            *reinterpret_cast<float2*>(&Y[(size_t)(row0 + 8) * 512 + col]) = o;
        }
    }
}

// ============================================================================
// Scores (bf16 3-term) + split-softmax partials
// ============================================================================
namespace {
constexpr int SC_QHI = 0;
constexpr int SC_QLO = 128 * KPS;
constexpr int SC_KHI = 2 * 128 * KPS;
constexpr int SC_KLO = 3 * 128 * KPS;
constexpr int SMEM_SCORES = 4 * 128 * KPS * 4;   // 73,728 bytes
}

__global__ void __launch_bounds__(256, 2) scores_mma(
    const float* __restrict__ Q, const float* __restrict__ K,
    const int* __restrict__ mask, const float* __restrict__ is_org,
    const float* __restrict__ Worg, const float* __restrict__ borg,
    float* __restrict__ att, float* __restrict__ pmax, float* __restrict__ psum)
{
    extern __shared__ uint32_t smu[];
    uint32_t* Qhi = smu + SC_QHI;
    uint32_t* Qlo = smu + SC_QLO;
    uint32_t* Khi = smu + SC_KHI;
    uint32_t* Klo = smu + SC_KLO;

    const int t = threadIdx.x, lane = t & 31, wid = t >> 5;
    const int g = lane >> 2, tig = lane & 3;
    const int wm = wid & 1, wn = wid >> 1;
    const int bh = blockIdx.z, b = bh >> 3, h = bh & 7;
    const int q0 = blockIdx.y * 128, k0g = blockIdx.x * 128;

    const float* Qg = Q + ((size_t)(b * S + q0)) * D + h * DK;
    const float* Kg = K + ((size_t)(b * S + k0g)) * D + h * DK;

#pragma unroll
    for (int i = t; i < 2048; i += 256) {
        const int row = i >> 4, c4 = (i & 15) * 4, p = c4 >> 1;
        float4 qv = *reinterpret_cast<const float4*>(Qg + (size_t)row * D + c4);
        float4 kv = *reinterpret_cast<const float4*>(Kg + (size_t)row * D + c4);
        uint2 h2, l2;
        split_bf16x2(qv.x, qv.y, h2.x, l2.x);
        split_bf16x2(qv.z, qv.w, h2.y, l2.y);
        *reinterpret_cast<uint2*>(&Qhi[row * KPS + p]) = h2;
        *reinterpret_cast<uint2*>(&Qlo[row * KPS + p]) = l2;
        split_bf16x2(kv.x, kv.y, h2.x, l2.x);
        split_bf16x2(kv.z, kv.w, h2.y, l2.y);
        *reinterpret_cast<uint2*>(&Khi[row * KPS + p]) = h2;
        *reinterpret_cast<uint2*>(&Klo[row * KPS + p]) = l2;
    }

    // ldmatrix base addresses
    const int am = lane >> 3, arm = lane & 7;
    const int bmat = (lane >> 3) & 1, brm = lane & 7;
    uint32_t aHi[4], aLo[4], bHi[4], bLo[4];
#pragma unroll
    for (int i = 0; i < 4; i++) {
        const int row = wm * 64 + i * 16 + (am & 1) * 8 + arm;
        const uint32_t off = (uint32_t)(row * KPS + (am >> 1) * 4) * 4u;
        aHi[i] = smaddr(Qhi) + off;
        aLo[i] = smaddr(Qlo) + off;
    }
#pragma unroll
    for (int j = 0; j < 4; j++) {
        const int row = wn * 32 + j * 8 + brm;
        const uint32_t off = (uint32_t)(row * KPS + bmat * 4) * 4u;
        bHi[j] = smaddr(Khi) + off;
        bLo[j] = smaddr(Klo) + off;
    }
    __syncthreads();

    float acc[4][4][4] = {};

#pragma unroll
    for (int ks = 0; ks < 4; ks++) {
        const uint32_t ko = ks * 32u;
        uint32_t ahi[4][4], alo[4][4];
#pragma unroll
        for (int i = 0; i < 4; i++) {
            ldmx4(ahi[i], aHi[i] + ko);
            ldmx4(alo[i], aLo[i] + ko);
        }
#pragma unroll
        for (int j = 0; j < 4; j++) {
            uint32_t bhi[2], blo[2];
            ldmx2(bhi, bHi[j] + ko);
            ldmx2(blo, bLo[j] + ko);
#pragma unroll
            for (int i = 0; i < 4; i++) {
                mma_bf16(acc[i][j], ahi[i], bhi);
                mma_bf16(acc[i][j], alo[i], bhi);
                mma_bf16(acc[i][j], ahi[i], blo);
            }
        }
    }

    // Finalize logits: scale + organic + mask
    const float worg = __ldg(Worg + h), bog = __ldg(borg + h);
    float og[4][2];
#pragma unroll
    for (int i = 0; i < 4; i++) {
#pragma unroll
        for (int hh = 0; hh < 2; hh++) {
            const int row = q0 + wm * 64 + i * 16 + g + hh * 8;
            og[i][hh] = __ldg(is_org + b * S + row) * worg + bog;
        }
    }
    int2 mj[4];
#pragma unroll
    for (int j = 0; j < 4; j++) {
        const int col = k0g + wn * 32 + j * 8 + 2 * tig;
        mj[j] = *reinterpret_cast<const int2*>(mask + b * S + col);
    }
#pragma unroll
    for (int i = 0; i < 4; i++) {
#pragma unroll
        for (int j = 0; j < 4; j++) {
            float v;
            v = acc[i][j][0] * 0.125f + og[i][0]; acc[i][j][0] = mj[j].x ? v : -1e9f;
            v = acc[i][j][1] * 0.125f + og[i][0]; acc[i][j][1] = mj[j].y ? v : -1e9f;
            v = acc[i][j][2] * 0.125f + og[i][1]; acc[i][j][2] = mj[j].x ? v : -1e9f;
            v = acc[i][j][3] * 0.125f + og[i][1]; acc[i][j][3] = mj[j].y ? v : -1e9f;
        }
    }

    // Store logits
#pragma unroll
    for (int i = 0; i < 4; i++) {
        const int row0 = q0 + wm * 64 + i * 16 + g;
#pragma unroll
        for (int j = 0; j < 4; j++) {
            const int col = k0g + wn * 32 + j * 8 + 2 * tig;
            float2 o;
            o.x = acc[i][j][0]; o.y = acc[i][j][1];
            *reinterpret_cast<float2*>(&att[((size_t)bh * S + row0) * S + col]) = o;
            o.x = acc[i][j][2]; o.y = acc[i][j][3];
            *reinterpret_cast<float2*>(&att[((size_t)bh * S + row0 + 8) * S + col]) = o;
        }
    }

    // Softmax partials per (row, 32-col warp tile)
    const int kwarp = blockIdx.x * 4 + wn;
#pragma unroll
    for (int i = 0; i < 4; i++) {
#pragma unroll
        for (int hh = 0; hh < 2; hh++) {
            float m = -1e30f;
#pragma unroll
            for (int j = 0; j < 4; j++)
                m = fmaxf(m, fmaxf(acc[i][j][hh * 2], acc[i][j][hh * 2 + 1]));
            m = fmaxf(m, __shfl_xor_sync(0xffffffffu, m, 1));
            m = fmaxf(m, __shfl_xor_sync(0xffffffffu, m, 2));
            float s = 0.0f;
#pragma unroll
            for (int j = 0; j < 4; j++)
                s += __expf(acc[i][j][hh * 2] - m) + __expf(acc[i][j][hh * 2 + 1] - m);
            s += __shfl_xor_sync(0xffffffffu, s, 1);
            s += __shfl_xor_sync(0xffffffffu, s, 2);
            if (tig == 0) {
                const size_t prow = (size_t)bh * S + q0 + wm * 64 + i * 16 + g + hh * 8;
                pmax[prow * 64 + kwarp] = m;
                psum[prow * 64 + kwarp] = s;
            }
        }
    }
}

// ============================================================================
// Row-stat reduce: 64 partials/row -> (M, 1/sum). One warp per row.
// ============================================================================
__global__ void __launch_bounds__(256) reduce_rows(
    const float* __restrict__ pmax, const float* __restrict__ psum,
    float* __restrict__ rowM, float* __restrict__ rowInv)
{
    const int wid = threadIdx.x >> 5, lane = threadIdx.x & 31;
    const size_t row = (size_t)blockIdx.x * 8 + wid;
    const float m0 = pmax[row * 64 + lane];
    const float m1 = pmax[row * 64 + lane + 32];
    float m = fmaxf(m0, m1);
#pragma unroll
    for (int o = 16; o; o >>= 1) m = fmaxf(m, __shfl_xor_sync(0xffffffffu, m, o));
    float s = psum[row * 64 + lane] * __expf(m0 - m)
            + psum[row * 64 + lane + 32] * __expf(m1 - m);
#pragma unroll
    for (int o = 16; o; o >>= 1) s += __shfl_xor_sync(0xffffffffu, s, o);
    if (lane == 0) {
        rowM[row] = m;
        rowInv[row] = 1.0f / s;
    }
}

// ============================================================================
// AV (bf16 3-term) with fused softmax normalization
// ============================================================================
namespace {
constexpr int AV_AHI = 0;
constexpr int AV_ALO = 128 * KPS;
constexpr int AV_VHI = 2 * 128 * KPS;
constexpr int AV_VLO = AV_VHI + 64 * KPS;
constexpr int AV_RM  = AV_VLO + 64 * KPS;
constexpr int AV_RI  = AV_RM + 128;
constexpr int SMEM_AV = (AV_RI + 128) * 4;      // 56,320 bytes
}

__global__ void __launch_bounds__(256, 2) av_mma(
    float* __restrict__ att, const float* __restrict__ V,
    const float* __restrict__ rowM, const float* __restrict__ rowInv,
    float* __restrict__ C)
{
    extern __shared__ uint32_t smu[];
    uint32_t* Ahi = smu + AV_AHI;
    uint32_t* Alo = smu + AV_ALO;
    uint32_t* Vhi = smu + AV_VHI;
    uint32_t* Vlo = smu + AV_VLO;
    float*    Rm  = reinterpret_cast<float*>(smu + AV_RM);
    float*    Ri  = reinterpret_cast<float*>(smu + AV_RI);

    const int t = threadIdx.x, lane = t & 31, wid = t >> 5;
    const int g = lane >> 2, tig = lane & 3;
    const int wm = wid & 3, wn = wid >> 2;
    const int bh = blockIdx.y, b = bh >> 3, h = bh & 7;
    const int q0 = blockIdx.x * 128;

    if (t < 128) {
        Rm[t] = rowM[(size_t)bh * S + q0 + t];
        Ri[t] = rowInv[(size_t)bh * S + q0 + t];
    }

    const int am = lane >> 3, arm = lane & 7;
    const int bmat = (lane >> 3) & 1, brm = lane & 7;
    uint32_t aHi[2], aLo[2], bHi[4], bLo[4];
#pragma unroll
    for (int i = 0; i < 2; i++) {
        const int row = wm * 32 + i * 16 + (am & 1) * 8 + arm;
        const uint32_t off = (uint32_t)(row * KPS + (am >> 1) * 4) * 4u;
        aHi[i] = smaddr(Ahi) + off;
        aLo[i] = smaddr(Alo) + off;
    }
#pragma unroll
    for (int j = 0; j < 4; j++) {
        const int row = wn * 32 + j * 8 + brm;
        const uint32_t off = (uint32_t)(row * KPS + bmat * 4) * 4u;
        bHi[j] = smaddr(Vhi) + off;
        bLo[j] = smaddr(Vlo) + off;
    }
    __syncthreads();

    float acc[2][4][4] = {};

    for (int kc = 0; kc < S; kc += 64) {
#pragma unroll
        for (int i = t; i < 2048; i += 256) {
            const int row = i >> 4, c4 = (i & 15) * 4, p4 = c4 >> 1;
            float* gp = &att[((size_t)bh * S + q0 + row) * S + kc + c4];
            float4 x = *reinterpret_cast<const float4*>(gp);
            const float M = Rm[row], Inv = Ri[row];
            float4 pp;
            pp.x = __expf(x.x - M) * Inv;
            pp.y = __expf(x.y - M) * Inv;
            pp.z = __expf(x.z - M) * Inv;
            pp.w = __expf(x.w - M) * Inv;
            *reinterpret_cast<float4*>(gp) = pp;
            uint2 h2, l2;
            split_bf16x2(pp.x, pp.y, h2.x, l2.x);
            split_bf16x2(pp.z, pp.w, h2.y, l2.y);
            *reinterpret_cast<uint2*>(&Ahi[row * KPS + p4]) = h2;
            *reinterpret_cast<uint2*>(&Alo[row * KPS + p4]) = l2;
        }
#pragma unroll
        for (int i = t; i < 512; i += 256) {
            const int dg = i & 15, kp = i >> 4;
            const float* vp = &V[(size_t)(b * S + kc + 2 * kp) * D + h * DK + dg * 4];
            float4 va = *reinterpret_cast<const float4*>(vp);
            float4 vb = *reinterpret_cast<const float4*>(vp + D);
            uint32_t hi, lo;
            split_bf16x2(va.x, vb.x, hi, lo);
            Vhi[(dg * 4 + 0) * KPS + kp] = hi; Vlo[(dg * 4 + 0) * KPS + kp] = lo;
            split_bf16x2(va.y, vb.y, hi, lo);
            Vhi[(dg * 4 + 1) * KPS + kp] = hi; Vlo[(dg * 4 + 1) * KPS + kp] = lo;
            split_bf16x2(va.z, vb.z, hi, lo);
            Vhi[(dg * 4 + 2) * KPS + kp] = hi; Vlo[(dg * 4 + 2) * KPS + kp] = lo;
            split_bf16x2(va.w, vb.w, hi, lo);
            Vhi[(dg * 4 + 3) * KPS + kp] = hi; Vlo[(dg * 4 + 3) * KPS + kp] = lo;
        }
        __syncthreads();

#pragma unroll
        for (int ks = 0; ks < 4; ks++) {
            const uint32_t ko = ks * 32u;
            uint32_t ahi[2][4], alo[2][4];
#pragma unroll
            for (int i = 0; i < 2; i++) {
                ldmx4(ahi[i], aHi[i] + ko);
                ldmx4(alo[i], aLo[i] + ko);
            }
#pragma unroll
            for (int j = 0; j < 4; j++) {
                uint32_t bhi[2], blo[2];
                ldmx2(bhi, bHi[j] + ko);
                ldmx2(blo, bLo[j] + ko);
#pragma unroll
                for (int i = 0; i < 2; i++) {
                    mma_bf16(acc[i][j], ahi[i], bhi);
                    mma_bf16(acc[i][j], alo[i], bhi);
                    mma_bf16(acc[i][j], ahi[i], blo);
                }
            }
        }
        __syncthreads();
    }

#pragma unroll
    for (int i = 0; i < 2; i++) {
        const int row0 = q0 + wm * 32 + i * 16 + g;
#pragma unroll
        for (int j = 0; j < 4; j++) {
            const int col = h * DK + wn * 32 + j * 8 + 2 * tig;
            float2 o;
            o.x = acc[i][j][0]; o.y = acc[i][j][1];
            *reinterpret_cast<float2*>(&C[(size_t)(b * S + row0) * D + col]) = o;
            o.x = acc[i][j][2]; o.y = acc[i][j][3];
            *reinterpret_cast<float2*>(&C[(size_t)(b * S + row0 + 8) * D + col]) = o;
        }
    }
}

// ---------------------------------------------------------------------------
extern "C" void kernel_launch(void* const* d_in, const int* in_sizes, int n_in,
                              void* d_out, int out_size)
{
    const float* query = (const float*)d_in[0];
    const float* key   = (const float*)d_in[1];
    const float* value = (const float*)d_in[2];
    const int*   mask  = (const int*)d_in[3];
    const float* isog  = (const float*)d_in[4];
    const float* Wq    = (const float*)d_in[5];
    const float* bq    = (const float*)d_in[6];
    const float* Wk    = (const float*)d_in[7];
    const float* bk    = (const float*)d_in[8];
    const float* Wv    = (const float*)d_in[9];
    const float* bv    = (const float*)d_in[10];
    const float* Wo    = (const float*)d_in[11];
    const float* bo    = (const float*)d_in[12];
    const float* Worg  = (const float*)d_in[13];
    const float* borg  = (const float*)d_in[14];

    float* out = (float*)d_out;

    float *qbuf, *kbuf, *vbuf, *cbuf, *pmax, *psum, *rowM, *rowInv;
    cudaGetSymbolAddress((void**)&qbuf, g_Q);
    cudaGetSymbolAddress((void**)&kbuf, g_K);
    cudaGetSymbolAddress((void**)&vbuf, g_V);
    cudaGetSymbolAddress((void**)&cbuf, g_C);
    cudaGetSymbolAddress((void**)&pmax, g_pmax);
    cudaGetSymbolAddress((void**)&psum, g_psum);
    cudaGetSymbolAddress((void**)&rowM, g_rowM);
    cudaGetSymbolAddress((void**)&rowInv, g_rowInv);

    const long long OUT_MAIN = (long long)B * S * D;
    const long long ATT_SZ   = (long long)B * H * S * S;
    float* att;
    if ((long long)out_size >= OUT_MAIN + ATT_SZ) {
        att = out + OUT_MAIN;
    } else {
        cudaGetSymbolAddress((void**)&att, g_att);
    }

    static bool attr_done = false;
    if (!attr_done) {
        cudaFuncSetAttribute(scores_mma, cudaFuncAttributeMaxDynamicSharedMemorySize, SMEM_SCORES);
        cudaFuncSetAttribute(av_mma, cudaFuncAttributeMaxDynamicSharedMemorySize, SMEM_AV);
        cudaFuncSetAttribute(gemm_mma, cudaFuncAttributeMaxDynamicSharedMemorySize, SMEM_GEMM);
        attr_done = true;
    }

    dim3 gg(4, 64);
    gemm_mma<<<gg, 256, SMEM_GEMM>>>(query, Wq, bq, qbuf);
    gemm_mma<<<gg, 256, SMEM_GEMM>>>(key,   Wk, bk, kbuf);
    gemm_mma<<<gg, 256, SMEM_GEMM>>>(value, Wv, bv, vbuf);

    dim3 gs(S / 128, S / 128, B * H);
    scores_mma<<<gs, 256, SMEM_SCORES>>>(qbuf, kbuf, mask, isog, Worg, borg, att, pmax, psum);

    reduce_rows<<<(B * H * S) / 8, 256>>>(pmax, psum, rowM, rowInv);

    dim3 ga(S / 128, B * H);
    av_mma<<<ga, 256, SMEM_AV>>>(att, vbuf, rowM, rowInv, cbuf);

    gemm_mma<<<gg, 256, SMEM_GEMM>>>(cbuf, Wo, bo, out);
}

// round 9
// speedup vs baseline: 1.6161x; 1.0880x over previous
#include <cuda_runtime.h>
#include <cstdint>

namespace {
constexpr int B = 4, S = 2048, D = 512, H = 8, DK = 64;
}

// Scratch (allocation-free rule: __device__ globals)
__device__ float g_Q[(size_t)B * S * D];
__device__ float g_K[(size_t)B * S * D];
__device__ float g_V[(size_t)B * S * D];
__device__ float g_C[(size_t)B * S * D];
__device__ float g_att[(size_t)B * H * S * S];
__device__ float g_rowM[(size_t)B * H * S];
__device__ float g_rowInv[(size_t)B * H * S];

// ============================================================================
// bf16 split, MMA, ldmatrix helpers (portable PTX — works on compute_103)
// ============================================================================
__device__ __forceinline__ void split_bf16x2(float x0, float x1, uint32_t& hi, uint32_t& lo) {
    asm("cvt.rn.bf16x2.f32 %0, %1, %2;" : "=r"(hi) : "f"(x1), "f"(x0));
    const float h0 = __uint_as_float(hi << 16);
    const float h1 = __uint_as_float(hi & 0xFFFF0000u);
    asm("cvt.rn.bf16x2.f32 %0, %1, %2;" : "=r"(lo) : "f"(x1 - h1), "f"(x0 - h0));
}
__device__ __forceinline__ void mma_bf16(float c[4], const uint32_t a[4], const uint32_t b[2]) {
    asm volatile(
        "mma.sync.aligned.m16n8k16.row.col.f32.bf16.bf16.f32 "
        "{%0,%1,%2,%3}, {%4,%5,%6,%7}, {%8,%9}, {%0,%1,%2,%3};"
        : "+f"(c[0]), "+f"(c[1]), "+f"(c[2]), "+f"(c[3])
        : "r"(a[0]), "r"(a[1]), "r"(a[2]), "r"(a[3]), "r"(b[0]), "r"(b[1]));
}
__device__ __forceinline__ void ldmx4(uint32_t r[4], uint32_t addr) {
    asm volatile("ldmatrix.sync.aligned.m8n8.x4.shared.b16 {%0,%1,%2,%3}, [%4];"
                 : "=r"(r[0]), "=r"(r[1]), "=r"(r[2]), "=r"(r[3]) : "r"(addr));
}
__device__ __forceinline__ void ldmx2(uint32_t r[2], uint32_t addr) {
    asm volatile("ldmatrix.sync.aligned.m8n8.x2.shared.b16 {%0,%1}, [%2];"
                 : "=r"(r[0]), "=r"(r[1]) : "r"(addr));
}
__device__ __forceinline__ uint32_t smaddr(const void* p) {
    return (uint32_t)__cvta_generic_to_shared(p);
}

namespace {
constexpr int KPS = 36;   // bf16x2-pair stride (padded; conflict-free)
}

// ============================================================================
// Projection GEMM (bf16 3-term): Y[M,512] = X @ W^T + bias  (unchanged R8)
// ============================================================================
namespace {
constexpr int GM_XHI = 0;
constexpr int GM_XLO = 128 * KPS;
constexpr int GM_WHI = 2 * 128 * KPS;
constexpr int GM_WLO = 3 * 128 * KPS;
constexpr int SMEM_GEMM = 4 * 128 * KPS * 4;     // 73,728 bytes
}

__global__ void __launch_bounds__(256, 2) gemm_mma(
    const float* __restrict__ X, const float* __restrict__ W,
    const float* __restrict__ bias, float* __restrict__ Y)
{
    extern __shared__ uint32_t smu[];
    uint32_t* Xhi = smu + GM_XHI;
    uint32_t* Xlo = smu + GM_XLO;
    uint32_t* Whi = smu + GM_WHI;
    uint32_t* Wlo = smu + GM_WLO;

    const int t = threadIdx.x, lane = t & 31, wid = t >> 5;
    const int g = lane >> 2, tig = lane & 3;
    const int wm = wid & 1, wn = wid >> 1;
    const int m0 = blockIdx.y * 128, n0 = blockIdx.x * 128;

    const int am = lane >> 3, arm = lane & 7;
    const int bmat = (lane >> 3) & 1, brm = lane & 7;
    uint32_t aHi[4], aLo[4], bHi[4], bLo[4];
#pragma unroll
    for (int i = 0; i < 4; i++) {
        const int row = wm * 64 + i * 16 + (am & 1) * 8 + arm;
        const uint32_t off = (uint32_t)(row * KPS + (am >> 1) * 4) * 4u;
        aHi[i] = smaddr(Xhi) + off;
        aLo[i] = smaddr(Xlo) + off;
    }
#pragma unroll
    for (int j = 0; j < 4; j++) {
        const int row = wn * 32 + j * 8 + brm;
        const uint32_t off = (uint32_t)(row * KPS + bmat * 4) * 4u;
        bHi[j] = smaddr(Whi) + off;
        bLo[j] = smaddr(Wlo) + off;
    }

    float acc[4][4][4] = {};

    for (int kc = 0; kc < 512; kc += 64) {
#pragma unroll
        for (int i = t; i < 2048; i += 256) {
            const int row = i >> 4, c4 = (i & 15) * 4, p = c4 >> 1;
            float4 xv = *reinterpret_cast<const float4*>(&X[(size_t)(m0 + row) * 512 + kc + c4]);
            float4 wv = *reinterpret_cast<const float4*>(&W[(size_t)(n0 + row) * 512 + kc + c4]);
            uint2 h, l;
            split_bf16x2(xv.x, xv.y, h.x, l.x);
            split_bf16x2(xv.z, xv.w, h.y, l.y);
            *reinterpret_cast<uint2*>(&Xhi[row * KPS + p]) = h;
            *reinterpret_cast<uint2*>(&Xlo[row * KPS + p]) = l;
            split_bf16x2(wv.x, wv.y, h.x, l.x);
            split_bf16x2(wv.z, wv.w, h.y, l.y);
            *reinterpret_cast<uint2*>(&Whi[row * KPS + p]) = h;
            *reinterpret_cast<uint2*>(&Wlo[row * KPS + p]) = l;
        }
        __syncthreads();

#pragma unroll
        for (int ks = 0; ks < 4; ks++) {
            const uint32_t ko = ks * 32u;
            uint32_t ahi[4][4], alo[4][4];
#pragma unroll
            for (int i = 0; i < 4; i++) {
                ldmx4(ahi[i], aHi[i] + ko);
                ldmx4(alo[i], aLo[i] + ko);
            }
#pragma unroll
            for (int j = 0; j < 4; j++) {
                uint32_t bhi[2], blo[2];
                ldmx2(bhi, bHi[j] + ko);
                ldmx2(blo, bLo[j] + ko);
#pragma unroll
                for (int i = 0; i < 4; i++) {
                    mma_bf16(acc[i][j], ahi[i], bhi);
                    mma_bf16(acc[i][j], alo[i], bhi);
                    mma_bf16(acc[i][j], ahi[i], blo);
                }
            }
        }
        __syncthreads();
    }

#pragma unroll
    for (int i = 0; i < 4; i++) {
        const int row0 = m0 + wm * 64 + i * 16 + g;
#pragma unroll
        for (int j = 0; j < 4; j++) {
            const int col = n0 + wn * 32 + j * 8 + 2 * tig;
            const float b0 = __ldg(bias + col), b1 = __ldg(bias + col + 1);
            float2 o;
            o.x = acc[i][j][0] + b0; o.y = acc[i][j][1] + b1;
            *reinterpret_cast<float2*>(&Y[(size_t)row0 * 512 + col]) = o;
            o.x = acc[i][j][2] + b0; o.y = acc[i][j][3] + b1;
            *reinterpret_cast<float2*>(&Y[(size_t)(row0 + 8) * 512 + col]) = o;
        }
    }
}

// ============================================================================
// stats_mma: per 128-row q-strip, stream all k-tiles (64 wide), compute
// logits in regs via bf16 3-term MMA, online (max, sumexp) -> rowM, rowInv.
// Warp layout: 4m x 2n (warp = 32 rows x 32 cols of each 64-col k-tile).
// ============================================================================
namespace {
constexpr int ST_QHI = 0;
constexpr int ST_QLO = 128 * KPS;
constexpr int ST_KHI = 2 * 128 * KPS;
constexpr int ST_KLO = ST_KHI + 64 * KPS;
constexpr int ST_RED = ST_KLO + 64 * KPS;           // float [128][2] m, then s
constexpr int SMEM_STATS = (ST_RED + 512) * 4;      // 57,344 bytes
}

__global__ void __launch_bounds__(256, 2) stats_mma(
    const float* __restrict__ Q, const float* __restrict__ K,
    const int* __restrict__ mask, const float* __restrict__ is_org,
    const float* __restrict__ Worg, const float* __restrict__ borg,
    float* __restrict__ rowM, float* __restrict__ rowInv)
{
    extern __shared__ uint32_t smu[];
    uint32_t* Qhi = smu + ST_QHI;
    uint32_t* Qlo = smu + ST_QLO;
    uint32_t* Khi = smu + ST_KHI;
    uint32_t* Klo = smu + ST_KLO;
    float* redM = reinterpret_cast<float*>(smu + ST_RED);   // [128][2]
    float* redS = redM + 256;                               // [128][2]

    const int t = threadIdx.x, lane = t & 31, wid = t >> 5;
    const int g = lane >> 2, tig = lane & 3;
    const int wm = wid & 3, wn = wid >> 2;
    const int bh = blockIdx.y, b = bh >> 3, h = bh & 7;
    const int q0 = blockIdx.x * 128;

    const float* Qg = Q + ((size_t)(b * S + q0)) * D + h * DK;
    const float* Kg = K + ((size_t)(b * S)) * D + h * DK;

    // Q tile split (once)
#pragma unroll
    for (int i = t; i < 2048; i += 256) {
        const int row = i >> 4, c4 = (i & 15) * 4, p = c4 >> 1;
        float4 qv = *reinterpret_cast<const float4*>(Qg + (size_t)row * D + c4);
        uint2 h2, l2;
        split_bf16x2(qv.x, qv.y, h2.x, l2.x);
        split_bf16x2(qv.z, qv.w, h2.y, l2.y);
        *reinterpret_cast<uint2*>(&Qhi[row * KPS + p]) = h2;
        *reinterpret_cast<uint2*>(&Qlo[row * KPS + p]) = l2;
    }

    // ldmatrix bases
    const int am = lane >> 3, arm = lane & 7;
    const int bmat = (lane >> 3) & 1, brm = lane & 7;
    uint32_t aHi[2], aLo[2], bHi[4], bLo[4];
#pragma unroll
    for (int i = 0; i < 2; i++) {
        const int row = wm * 32 + i * 16 + (am & 1) * 8 + arm;
        const uint32_t off = (uint32_t)(row * KPS + (am >> 1) * 4) * 4u;
        aHi[i] = smaddr(Qhi) + off;
        aLo[i] = smaddr(Qlo) + off;
    }
#pragma unroll
    for (int j = 0; j < 4; j++) {
        const int row = wn * 32 + j * 8 + brm;
        const uint32_t off = (uint32_t)(row * KPS + bmat * 4) * 4u;
        bHi[j] = smaddr(Khi) + off;
        bLo[j] = smaddr(Klo) + off;
    }

    const float worg = __ldg(Worg + h), bog = __ldg(borg + h);
    float og[2][2];
#pragma unroll
    for (int i = 0; i < 2; i++)
#pragma unroll
        for (int hh = 0; hh < 2; hh++)
            og[i][hh] = __ldg(is_org + b * S + q0 + wm * 32 + i * 16 + g + hh * 8) * worg + bog;

    float rm[2][2], rs[2][2];
#pragma unroll
    for (int i = 0; i < 2; i++)
#pragma unroll
        for (int hh = 0; hh < 2; hh++) { rm[i][hh] = -1e30f; rs[i][hh] = 0.0f; }

    for (int kt = 0; kt < 32; kt++) {
        // K tile (64 rows x 64) split
#pragma unroll
        for (int i = t; i < 1024; i += 256) {
            const int row = i >> 4, c4 = (i & 15) * 4, p = c4 >> 1;
            float4 kv = *reinterpret_cast<const float4*>(
                Kg + (size_t)(kt * 64 + row) * D + c4);
            uint2 h2, l2;
            split_bf16x2(kv.x, kv.y, h2.x, l2.x);
            split_bf16x2(kv.z, kv.w, h2.y, l2.y);
            *reinterpret_cast<uint2*>(&Khi[row * KPS + p]) = h2;
            *reinterpret_cast<uint2*>(&Klo[row * KPS + p]) = l2;
        }
        __syncthreads();

        float acc[2][4][4] = {};
#pragma unroll
        for (int ks = 0; ks < 4; ks++) {
            const uint32_t ko = ks * 32u;
            uint32_t ahi[2][4], alo[2][4];
#pragma unroll
            for (int i = 0; i < 2; i++) { ldmx4(ahi[i], aHi[i] + ko); ldmx4(alo[i], aLo[i] + ko); }
#pragma unroll
            for (int j = 0; j < 4; j++) {
                uint32_t bhi[2], blo[2];
                ldmx2(bhi, bHi[j] + ko);
                ldmx2(blo, bLo[j] + ko);
#pragma unroll
                for (int i = 0; i < 2; i++) {
                    mma_bf16(acc[i][j], ahi[i], bhi);
                    mma_bf16(acc[i][j], alo[i], bhi);
                    mma_bf16(acc[i][j], ahi[i], blo);
                }
            }
        }

        int2 mj[4];
#pragma unroll
        for (int j = 0; j < 4; j++)
            mj[j] = *reinterpret_cast<const int2*>(mask + b * S + kt * 64 + wn * 32 + j * 8 + 2 * tig);

#pragma unroll
        for (int i = 0; i < 2; i++) {
#pragma unroll
            for (int j = 0; j < 4; j++) {
                float v;
                v = acc[i][j][0] * 0.125f + og[i][0]; acc[i][j][0] = mj[j].x ? v : -1e9f;
                v = acc[i][j][1] * 0.125f + og[i][0]; acc[i][j][1] = mj[j].y ? v : -1e9f;
                v = acc[i][j][2] * 0.125f + og[i][1]; acc[i][j][2] = mj[j].x ? v : -1e9f;
                v = acc[i][j][3] * 0.125f + og[i][1]; acc[i][j][3] = mj[j].y ? v : -1e9f;
            }
        }

        // Online stats per row fragment
#pragma unroll
        for (int i = 0; i < 2; i++) {
#pragma unroll
            for (int hh = 0; hh < 2; hh++) {
                float mt = -1e30f;
#pragma unroll
                for (int j = 0; j < 4; j++)
                    mt = fmaxf(mt, fmaxf(acc[i][j][hh * 2], acc[i][j][hh * 2 + 1]));
                mt = fmaxf(mt, __shfl_xor_sync(0xffffffffu, mt, 1));
                mt = fmaxf(mt, __shfl_xor_sync(0xffffffffu, mt, 2));
                const float mnew = fmaxf(rm[i][hh], mt);
                float st = 0.0f;
#pragma unroll
                for (int j = 0; j < 4; j++)
                    st += __expf(acc[i][j][hh * 2] - mnew) + __expf(acc[i][j][hh * 2 + 1] - mnew);
                st += __shfl_xor_sync(0xffffffffu, st, 1);
                st += __shfl_xor_sync(0xffffffffu, st, 2);
                rs[i][hh] = rs[i][hh] * __expf(rm[i][hh] - mnew) + st;
                rm[i][hh] = mnew;
            }
        }
        __syncthreads();
    }

    // Combine the two n-warps per row
    if (tig == 0) {
#pragma unroll
        for (int i = 0; i < 2; i++)
#pragma unroll
            for (int hh = 0; hh < 2; hh++) {
                const int r = wm * 32 + i * 16 + g + hh * 8;
                redM[r * 2 + wn] = rm[i][hh];
                redS[r * 2 + wn] = rs[i][hh];
            }
    }
    __syncthreads();
    if (t < 128) {
        const float m0 = redM[t * 2], m1 = redM[t * 2 + 1];
        const float m = fmaxf(m0, m1);
        const float s = redS[t * 2] * __expf(m0 - m) + redS[t * 2 + 1] * __expf(m1 - m);
        rowM[(size_t)bh * S + q0 + t] = m;
        rowInv[(size_t)bh * S + q0 + t] = 1.0f / s;
    }
}

// ============================================================================
// av_fused: recompute QK logits per k-tile, p = exp(x-M)*Inv, write p to att
// (the only 537MB write), stage p in smem, AV MMA. Warp layout 4m x 2n.
// ============================================================================
namespace {
constexpr int AF_QHI = 0;
constexpr int AF_QLO = 128 * KPS;
constexpr int AF_KHI = 2 * 128 * KPS;
constexpr int AF_KLO = AF_KHI + 64 * KPS;
constexpr int AF_VHI = AF_KLO + 64 * KPS;
constexpr int AF_VLO = AF_VHI + 64 * KPS;
constexpr int AF_PHI = AF_VLO + 64 * KPS;
constexpr int AF_PLO = AF_PHI + 128 * KPS;
constexpr int AF_RM  = AF_PLO + 128 * KPS;
constexpr int AF_RI  = AF_RM + 128;
constexpr int SMEM_AF = (AF_RI + 128) * 4;     // 111,616 bytes
}

__global__ void __launch_bounds__(256, 2) av_fused(
    const float* __restrict__ Q, const float* __restrict__ K,
    const float* __restrict__ V,
    const int* __restrict__ mask, const float* __restrict__ is_org,
    const float* __restrict__ Worg, const float* __restrict__ borg,
    const float* __restrict__ rowM, const float* __restrict__ rowInv,
    float* __restrict__ att, float* __restrict__ C)
{
    extern __shared__ uint32_t smu[];
    uint32_t* Qhi = smu + AF_QHI;
    uint32_t* Qlo = smu + AF_QLO;
    uint32_t* Khi = smu + AF_KHI;
    uint32_t* Klo = smu + AF_KLO;
    uint32_t* Vhi = smu + AF_VHI;
    uint32_t* Vlo = smu + AF_VLO;
    uint32_t* Phi = smu + AF_PHI;
    uint32_t* Plo = smu + AF_PLO;
    float*    Rm  = reinterpret_cast<float*>(smu + AF_RM);
    float*    Ri  = reinterpret_cast<float*>(smu + AF_RI);

    const int t = threadIdx.x, lane = t & 31, wid = t >> 5;
    const int g = lane >> 2, tig = lane & 3;
    const int wm = wid & 3, wn = wid >> 2;
    const int bh = blockIdx.y, b = bh >> 3, h = bh & 7;
    const int q0 = blockIdx.x * 128;

    const float* Qg = Q + ((size_t)(b * S + q0)) * D + h * DK;
    const float* Kg = K + ((size_t)(b * S)) * D + h * DK;
    const float* Vg = V + ((size_t)(b * S)) * D + h * DK;

    if (t < 128) {
        Rm[t] = rowM[(size_t)bh * S + q0 + t];
        Ri[t] = rowInv[(size_t)bh * S + q0 + t];
    }
#pragma unroll
    for (int i = t; i < 2048; i += 256) {
        const int row = i >> 4, c4 = (i & 15) * 4, p = c4 >> 1;
        float4 qv = *reinterpret_cast<const float4*>(Qg + (size_t)row * D + c4);
        uint2 h2, l2;
        split_bf16x2(qv.x, qv.y, h2.x, l2.x);
        split_bf16x2(qv.z, qv.w, h2.y, l2.y);
        *reinterpret_cast<uint2*>(&Qhi[row * KPS + p]) = h2;
        *reinterpret_cast<uint2*>(&Qlo[row * KPS + p]) = l2;
    }

    const int am = lane >> 3, arm = lane & 7;
    const int bmat = (lane >> 3) & 1, brm = lane & 7;
    uint32_t aQhi[2], aQlo[2], aPhi[2], aPlo[2], bKhi[4], bKlo[4], bVhi[4], bVlo[4];
#pragma unroll
    for (int i = 0; i < 2; i++) {
        const int row = wm * 32 + i * 16 + (am & 1) * 8 + arm;
        const uint32_t off = (uint32_t)(row * KPS + (am >> 1) * 4) * 4u;
        aQhi[i] = smaddr(Qhi) + off; aQlo[i] = smaddr(Qlo) + off;
        aPhi[i] = smaddr(Phi) + off; aPlo[i] = smaddr(Plo) + off;
    }
#pragma unroll
    for (int j = 0; j < 4; j++) {
        const int row = wn * 32 + j * 8 + brm;
        const uint32_t off = (uint32_t)(row * KPS + bmat * 4) * 4u;
        bKhi[j] = smaddr(Khi) + off; bKlo[j] = smaddr(Klo) + off;
        bVhi[j] = smaddr(Vhi) + off; bVlo[j] = smaddr(Vlo) + off;
    }

    const float worg = __ldg(Worg + h), bog = __ldg(borg + h);
    float og[2][2];
#pragma unroll
    for (int i = 0; i < 2; i++)
#pragma unroll
        for (int hh = 0; hh < 2; hh++)
            og[i][hh] = __ldg(is_org + b * S + q0 + wm * 32 + i * 16 + g + hh * 8) * worg + bog;

    float accAV[2][4][4] = {};

    for (int kt = 0; kt < 32; kt++) {
        // K tile + V tile (split; V transposed to [d][kp])
#pragma unroll
        for (int i = t; i < 1024; i += 256) {
            const int row = i >> 4, c4 = (i & 15) * 4, p = c4 >> 1;
            float4 kv = *reinterpret_cast<const float4*>(
                Kg + (size_t)(kt * 64 + row) * D + c4);
            uint2 h2, l2;
            split_bf16x2(kv.x, kv.y, h2.x, l2.x);
            split_bf16x2(kv.z, kv.w, h2.y, l2.y);
            *reinterpret_cast<uint2*>(&Khi[row * KPS + p]) = h2;
            *reinterpret_cast<uint2*>(&Klo[row * KPS + p]) = l2;
        }
#pragma unroll
        for (int i = t; i < 512; i += 256) {
            const int dg = i & 15, kp = i >> 4;
            const float* vp = Vg + (size_t)(kt * 64 + 2 * kp) * D + dg * 4;
            float4 va = *reinterpret_cast<const float4*>(vp);
            float4 vb = *reinterpret_cast<const float4*>(vp + D);
            uint32_t hi, lo;
            split_bf16x2(va.x, vb.x, hi, lo);
            Vhi[(dg * 4 + 0) * KPS + kp] = hi; Vlo[(dg * 4 + 0) * KPS + kp] = lo;
            split_bf16x2(va.y, vb.y, hi, lo);
            Vhi[(dg * 4 + 1) * KPS + kp] = hi; Vlo[(dg * 4 + 1) * KPS + kp] = lo;
            split_bf16x2(va.z, vb.z, hi, lo);
            Vhi[(dg * 4 + 2) * KPS + kp] = hi; Vlo[(dg * 4 + 2) * KPS + kp] = lo;
            split_bf16x2(va.w, vb.w, hi, lo);
            Vhi[(dg * 4 + 3) * KPS + kp] = hi; Vlo[(dg * 4 + 3) * KPS + kp] = lo;
        }
        __syncthreads();

        // QK logits (bitwise identical to stats_mma)
        float acc[2][4][4] = {};
#pragma unroll
        for (int ks = 0; ks < 4; ks++) {
            const uint32_t ko = ks * 32u;
            uint32_t ahi[2][4], alo[2][4];
#pragma unroll
            for (int i = 0; i < 2; i++) { ldmx4(ahi[i], aQhi[i] + ko); ldmx4(alo[i], aQlo[i] + ko); }
#pragma unroll
            for (int j = 0; j < 4; j++) {
                uint32_t bhi[2], blo[2];
                ldmx2(bhi, bKhi[j] + ko);
                ldmx2(blo, bKlo[j] + ko);
#pragma unroll
                for (int i = 0; i < 2; i++) {
                    mma_bf16(acc[i][j], ahi[i], bhi);
                    mma_bf16(acc[i][j], alo[i], bhi);
                    mma_bf16(acc[i][j], ahi[i], blo);
                }
            }
        }

        int2 mj[4];
#pragma unroll
        for (int j = 0; j < 4; j++)
            mj[j] = *reinterpret_cast<const int2*>(mask + b * S + kt * 64 + wn * 32 + j * 8 + 2 * tig);

        // p = exp(x - M) * Inv; write to att; stage split p to smem
#pragma unroll
        for (int i = 0; i < 2; i++) {
#pragma unroll
            for (int hh = 0; hh < 2; hh++) {
                const int r = wm * 32 + i * 16 + g + hh * 8;
                const float M = Rm[r], Inv = Ri[r];
                const float ogv = og[i][hh];
                float* orow = &att[((size_t)bh * S + q0 + r) * S + kt * 64 + wn * 32 + 2 * tig];
#pragma unroll
                for (int j = 0; j < 4; j++) {
                    float x0 = acc[i][j][hh * 2]     * 0.125f + ogv;
                    float x1 = acc[i][j][hh * 2 + 1] * 0.125f + ogv;
                    x0 = mj[j].x ? x0 : -1e9f;
                    x1 = mj[j].y ? x1 : -1e9f;
                    const float p0 = __expf(x0 - M) * Inv;
                    const float p1 = __expf(x1 - M) * Inv;
                    float2 o; o.x = p0; o.y = p1;
                    *reinterpret_cast<float2*>(orow + j * 8) = o;
                    uint32_t hi, lo;
                    split_bf16x2(p0, p1, hi, lo);
                    const int pi = wn * 16 + j * 4 + tig;
                    Phi[r * KPS + pi] = hi;
                    Plo[r * KPS + pi] = lo;
                }
            }
        }
        __syncthreads();

        // AV: accAV += P(128x64) @ V(64x64)
#pragma unroll
        for (int ks = 0; ks < 4; ks++) {
            const uint32_t ko = ks * 32u;
            uint32_t ahi[2][4], alo[2][4];
#pragma unroll
            for (int i = 0; i < 2; i++) { ldmx4(ahi[i], aPhi[i] + ko); ldmx4(alo[i], aPlo[i] + ko); }
#pragma unroll
            for (int j = 0; j < 4; j++) {
                uint32_t bhi[2], blo[2];
                ldmx2(bhi, bVhi[j] + ko);
                ldmx2(blo, bVlo[j] + ko);
#pragma unroll
                for (int i = 0; i < 2; i++) {
                    mma_bf16(accAV[i][j], ahi[i], bhi);
                    mma_bf16(accAV[i][j], alo[i], bhi);
                    mma_bf16(accAV[i][j], ahi[i], blo);
                }
            }
        }
        __syncthreads();
    }

#pragma unroll
    for (int i = 0; i < 2; i++) {
        const int row0 = q0 + wm * 32 + i * 16 + g;
#pragma unroll
        for (int j = 0; j < 4; j++) {
            const int col = h * DK + wn * 32 + j * 8 + 2 * tig;
            float2 o;
            o.x = accAV[i][j][0]; o.y = accAV[i][j][1];
            *reinterpret_cast<float2*>(&C[(size_t)(b * S + row0) * D + col]) = o;
            o.x = accAV[i][j][2]; o.y = accAV[i][j][3];
            *reinterpret_cast<float2*>(&C[(size_t)(b * S + row0 + 8) * D + col]) = o;
        }
    }
}

// ---------------------------------------------------------------------------
extern "C" void kernel_launch(void* const* d_in, const int* in_sizes, int n_in,
                              void* d_out, int out_size)
{
    const float* query = (const float*)d_in[0];
    const float* key   = (const float*)d_in[1];
    const float* value = (const float*)d_in[2];
    const int*   mask  = (const int*)d_in[3];
    const float* isog  = (const float*)d_in[4];
    const float* Wq    = (const float*)d_in[5];
    const float* bq    = (const float*)d_in[6];
    const float* Wk    = (const float*)d_in[7];
    const float* bk    = (const float*)d_in[8];
    const float* Wv    = (const float*)d_in[9];
    const float* bv    = (const float*)d_in[10];
    const float* Wo    = (const float*)d_in[11];
    const float* bo    = (const float*)d_in[12];
    const float* Worg  = (const float*)d_in[13];
    const float* borg  = (const float*)d_in[14];

    float* out = (float*)d_out;

    float *qbuf, *kbuf, *vbuf, *cbuf, *rowM, *rowInv;
    cudaGetSymbolAddress((void**)&qbuf, g_Q);
    cudaGetSymbolAddress((void**)&kbuf, g_K);
    cudaGetSymbolAddress((void**)&vbuf, g_V);
    cudaGetSymbolAddress((void**)&cbuf, g_C);
    cudaGetSymbolAddress((void**)&rowM, g_rowM);
    cudaGetSymbolAddress((void**)&rowInv, g_rowInv);

    const long long OUT_MAIN = (long long)B * S * D;
    const long long ATT_SZ   = (long long)B * H * S * S;
    float* att;
    if ((long long)out_size >= OUT_MAIN + ATT_SZ) {
        att = out + OUT_MAIN;
    } else {
        cudaGetSymbolAddress((void**)&att, g_att);
    }

    static bool attr_done = false;
    if (!attr_done) {
        cudaFuncSetAttribute(gemm_mma,  cudaFuncAttributeMaxDynamicSharedMemorySize, SMEM_GEMM);
        cudaFuncSetAttribute(stats_mma, cudaFuncAttributeMaxDynamicSharedMemorySize, SMEM_STATS);
        cudaFuncSetAttribute(av_fused,  cudaFuncAttributeMaxDynamicSharedMemorySize, SMEM_AF);
        attr_done = true;
    }

    dim3 gg(4, 64);
    gemm_mma<<<gg, 256, SMEM_GEMM>>>(query, Wq, bq, qbuf);
    gemm_mma<<<gg, 256, SMEM_GEMM>>>(key,   Wk, bk, kbuf);
    gemm_mma<<<gg, 256, SMEM_GEMM>>>(value, Wv, bv, vbuf);

    dim3 gf(S / 128, B * H);
    stats_mma<<<gf, 256, SMEM_STATS>>>(qbuf, kbuf, mask, isog, Worg, borg, rowM, rowInv);

    av_fused<<<gf, 256, SMEM_AF>>>(qbuf, kbuf, vbuf, mask, isog, Worg, borg,
                                   rowM, rowInv, att, cbuf);

    gemm_mma<<<gg, 256, SMEM_GEMM>>>(cbuf, Wo, bo, out);
}

// round 10
// speedup vs baseline: 1.7268x; 1.0685x over previous
#include <cuda_runtime.h>
#include <cstdint>

namespace {
constexpr int B = 4, S = 2048, D = 512, H = 8, DK = 64;
}

// Scratch (allocation-free rule: __device__ globals)
__device__ float g_Q[(size_t)B * S * D];
__device__ float g_K[(size_t)B * S * D];
__device__ float g_V[(size_t)B * S * D];
__device__ float g_C[(size_t)B * S * D];
__device__ float g_att[(size_t)B * H * S * S];
__device__ float g_rowM[(size_t)B * H * S];
__device__ float g_rowInv[(size_t)B * H * S];

// ============================================================================
// bf16 split, MMA, ldmatrix helpers (portable PTX — works on compute_103)
// ============================================================================
__device__ __forceinline__ void split_bf16x2(float x0, float x1, uint32_t& hi, uint32_t& lo) {
    asm("cvt.rn.bf16x2.f32 %0, %1, %2;" : "=r"(hi) : "f"(x1), "f"(x0));
    const float h0 = __uint_as_float(hi << 16);
    const float h1 = __uint_as_float(hi & 0xFFFF0000u);
    asm("cvt.rn.bf16x2.f32 %0, %1, %2;" : "=r"(lo) : "f"(x1 - h1), "f"(x0 - h0));
}
__device__ __forceinline__ void mma_bf16(float c[4], const uint32_t a[4], const uint32_t b[2]) {
    asm volatile(
        "mma.sync.aligned.m16n8k16.row.col.f32.bf16.bf16.f32 "
        "{%0,%1,%2,%3}, {%4,%5,%6,%7}, {%8,%9}, {%0,%1,%2,%3};"
        : "+f"(c[0]), "+f"(c[1]), "+f"(c[2]), "+f"(c[3])
        : "r"(a[0]), "r"(a[1]), "r"(a[2]), "r"(a[3]), "r"(b[0]), "r"(b[1]));
}
__device__ __forceinline__ void ldmx4(uint32_t r[4], uint32_t addr) {
    asm volatile("ldmatrix.sync.aligned.m8n8.x4.shared.b16 {%0,%1,%2,%3}, [%4];"
                 : "=r"(r[0]), "=r"(r[1]), "=r"(r[2]), "=r"(r[3]) : "r"(addr));
}
__device__ __forceinline__ void ldmx2(uint32_t r[2], uint32_t addr) {
    asm volatile("ldmatrix.sync.aligned.m8n8.x2.shared.b16 {%0,%1}, [%2];"
                 : "=r"(r[0]), "=r"(r[1]) : "r"(addr));
}
__device__ __forceinline__ uint32_t smaddr(const void* p) {
    return (uint32_t)__cvta_generic_to_shared(p);
}

namespace {
constexpr int KPS = 36;   // bf16x2-pair stride (padded; conflict-free)
}

// ============================================================================
// Projection GEMM (bf16 3-term): Y[M,512] = X @ W^T + bias  (unchanged)
// ============================================================================
namespace {
constexpr int GM_XHI = 0;
constexpr int GM_XLO = 128 * KPS;
constexpr int GM_WHI = 2 * 128 * KPS;
constexpr int GM_WLO = 3 * 128 * KPS;
constexpr int SMEM_GEMM = 4 * 128 * KPS * 4;     // 73,728 bytes
}

__global__ void __launch_bounds__(256, 2) gemm_mma(
    const float* __restrict__ X, const float* __restrict__ W,
    const float* __restrict__ bias, float* __restrict__ Y)
{
    extern __shared__ uint32_t smu[];
    uint32_t* Xhi = smu + GM_XHI;
    uint32_t* Xlo = smu + GM_XLO;
    uint32_t* Whi = smu + GM_WHI;
    uint32_t* Wlo = smu + GM_WLO;

    const int t = threadIdx.x, lane = t & 31, wid = t >> 5;
    const int g = lane >> 2, tig = lane & 3;
    const int wm = wid & 1, wn = wid >> 1;
    const int m0 = blockIdx.y * 128, n0 = blockIdx.x * 128;

    const int am = lane >> 3, arm = lane & 7;
    const int bmat = (lane >> 3) & 1, brm = lane & 7;
    uint32_t aHi[4], aLo[4], bHi[4], bLo[4];
#pragma unroll
    for (int i = 0; i < 4; i++) {
        const int row = wm * 64 + i * 16 + (am & 1) * 8 + arm;
        const uint32_t off = (uint32_t)(row * KPS + (am >> 1) * 4) * 4u;
        aHi[i] = smaddr(Xhi) + off;
        aLo[i] = smaddr(Xlo) + off;
    }
#pragma unroll
    for (int j = 0; j < 4; j++) {
        const int row = wn * 32 + j * 8 + brm;
        const uint32_t off = (uint32_t)(row * KPS + bmat * 4) * 4u;
        bHi[j] = smaddr(Whi) + off;
        bLo[j] = smaddr(Wlo) + off;
    }

    float acc[4][4][4] = {};

    for (int kc = 0; kc < 512; kc += 64) {
#pragma unroll
        for (int i = t; i < 2048; i += 256) {
            const int row = i >> 4, c4 = (i & 15) * 4, p = c4 >> 1;
            float4 xv = *reinterpret_cast<const float4*>(&X[(size_t)(m0 + row) * 512 + kc + c4]);
            float4 wv = *reinterpret_cast<const float4*>(&W[(size_t)(n0 + row) * 512 + kc + c4]);
            uint2 h, l;
            split_bf16x2(xv.x, xv.y, h.x, l.x);
            split_bf16x2(xv.z, xv.w, h.y, l.y);
            *reinterpret_cast<uint2*>(&Xhi[row * KPS + p]) = h;
            *reinterpret_cast<uint2*>(&Xlo[row * KPS + p]) = l;
            split_bf16x2(wv.x, wv.y, h.x, l.x);
            split_bf16x2(wv.z, wv.w, h.y, l.y);
            *reinterpret_cast<uint2*>(&Whi[row * KPS + p]) = h;
            *reinterpret_cast<uint2*>(&Wlo[row * KPS + p]) = l;
        }
        __syncthreads();

#pragma unroll
        for (int ks = 0; ks < 4; ks++) {
            const uint32_t ko = ks * 32u;
            uint32_t ahi[4][4], alo[4][4];
#pragma unroll
            for (int i = 0; i < 4; i++) {
                ldmx4(ahi[i], aHi[i] + ko);
                ldmx4(alo[i], aLo[i] + ko);
            }
#pragma unroll
            for (int j = 0; j < 4; j++) {
                uint32_t bhi[2], blo[2];
                ldmx2(bhi, bHi[j] + ko);
                ldmx2(blo, bLo[j] + ko);
#pragma unroll
                for (int i = 0; i < 4; i++) {
                    mma_bf16(acc[i][j], ahi[i], bhi);
                    mma_bf16(acc[i][j], alo[i], bhi);
                    mma_bf16(acc[i][j], ahi[i], blo);
                }
            }
        }
        __syncthreads();
    }

#pragma unroll
    for (int i = 0; i < 4; i++) {
        const int row0 = m0 + wm * 64 + i * 16 + g;
#pragma unroll
        for (int j = 0; j < 4; j++) {
            const int col = n0 + wn * 32 + j * 8 + 2 * tig;
            const float b0 = __ldg(bias + col), b1 = __ldg(bias + col + 1);
            float2 o;
            o.x = acc[i][j][0] + b0; o.y = acc[i][j][1] + b1;
            *reinterpret_cast<float2*>(&Y[(size_t)row0 * 512 + col]) = o;
            o.x = acc[i][j][2] + b0; o.y = acc[i][j][3] + b1;
            *reinterpret_cast<float2*>(&Y[(size_t)(row0 + 8) * 512 + col]) = o;
        }
    }
}

// ============================================================================
// stats_mma: online (max, sumexp) over streamed k-tiles -> rowM, rowInv
// (unchanged from R9)
// ============================================================================
namespace {
constexpr int ST_QHI = 0;
constexpr int ST_QLO = 128 * KPS;
constexpr int ST_KHI = 2 * 128 * KPS;
constexpr int ST_KLO = ST_KHI + 64 * KPS;
constexpr int ST_RED = ST_KLO + 64 * KPS;
constexpr int SMEM_STATS = (ST_RED + 512) * 4;      // 57,344 bytes
}

__global__ void __launch_bounds__(256, 2) stats_mma(
    const float* __restrict__ Q, const float* __restrict__ K,
    const int* __restrict__ mask, const float* __restrict__ is_org,
    const float* __restrict__ Worg, const float* __restrict__ borg,
    float* __restrict__ rowM, float* __restrict__ rowInv)
{
    extern __shared__ uint32_t smu[];
    uint32_t* Qhi = smu + ST_QHI;
    uint32_t* Qlo = smu + ST_QLO;
    uint32_t* Khi = smu + ST_KHI;
    uint32_t* Klo = smu + ST_KLO;
    float* redM = reinterpret_cast<float*>(smu + ST_RED);
    float* redS = redM + 256;

    const int t = threadIdx.x, lane = t & 31, wid = t >> 5;
    const int g = lane >> 2, tig = lane & 3;
    const int wm = wid & 3, wn = wid >> 2;
    const int bh = blockIdx.y, b = bh >> 3, h = bh & 7;
    const int q0 = blockIdx.x * 128;

    const float* Qg = Q + ((size_t)(b * S + q0)) * D + h * DK;
    const float* Kg = K + ((size_t)(b * S)) * D + h * DK;

#pragma unroll
    for (int i = t; i < 2048; i += 256) {
        const int row = i >> 4, c4 = (i & 15) * 4, p = c4 >> 1;
        float4 qv = *reinterpret_cast<const float4*>(Qg + (size_t)row * D + c4);
        uint2 h2, l2;
        split_bf16x2(qv.x, qv.y, h2.x, l2.x);
        split_bf16x2(qv.z, qv.w, h2.y, l2.y);
        *reinterpret_cast<uint2*>(&Qhi[row * KPS + p]) = h2;
        *reinterpret_cast<uint2*>(&Qlo[row * KPS + p]) = l2;
    }

    const int am = lane >> 3, arm = lane & 7;
    const int bmat = (lane >> 3) & 1, brm = lane & 7;
    uint32_t aHi[2], aLo[2], bHi[4], bLo[4];
#pragma unroll
    for (int i = 0; i < 2; i++) {
        const int row = wm * 32 + i * 16 + (am & 1) * 8 + arm;
        const uint32_t off = (uint32_t)(row * KPS + (am >> 1) * 4) * 4u;
        aHi[i] = smaddr(Qhi) + off;
        aLo[i] = smaddr(Qlo) + off;
    }
#pragma unroll
    for (int j = 0; j < 4; j++) {
        const int row = wn * 32 + j * 8 + brm;
        const uint32_t off = (uint32_t)(row * KPS + bmat * 4) * 4u;
        bHi[j] = smaddr(Khi) + off;
        bLo[j] = smaddr(Klo) + off;
    }

    const float worg = __ldg(Worg + h), bog = __ldg(borg + h);
    float og[2][2];
#pragma unroll
    for (int i = 0; i < 2; i++)
#pragma unroll
        for (int hh = 0; hh < 2; hh++)
            og[i][hh] = __ldg(is_org + b * S + q0 + wm * 32 + i * 16 + g + hh * 8) * worg + bog;

    float rm[2][2], rs[2][2];
#pragma unroll
    for (int i = 0; i < 2; i++)
#pragma unroll
        for (int hh = 0; hh < 2; hh++) { rm[i][hh] = -1e30f; rs[i][hh] = 0.0f; }

    for (int kt = 0; kt < 32; kt++) {
#pragma unroll
        for (int i = t; i < 1024; i += 256) {
            const int row = i >> 4, c4 = (i & 15) * 4, p = c4 >> 1;
            float4 kv = *reinterpret_cast<const float4*>(
                Kg + (size_t)(kt * 64 + row) * D + c4);
            uint2 h2, l2;
            split_bf16x2(kv.x, kv.y, h2.x, l2.x);
            split_bf16x2(kv.z, kv.w, h2.y, l2.y);
            *reinterpret_cast<uint2*>(&Khi[row * KPS + p]) = h2;
            *reinterpret_cast<uint2*>(&Klo[row * KPS + p]) = l2;
        }
        __syncthreads();

        float acc[2][4][4] = {};
#pragma unroll
        for (int ks = 0; ks < 4; ks++) {
            const uint32_t ko = ks * 32u;
            uint32_t ahi[2][4], alo[2][4];
#pragma unroll
            for (int i = 0; i < 2; i++) { ldmx4(ahi[i], aHi[i] + ko); ldmx4(alo[i], aLo[i] + ko); }
#pragma unroll
            for (int j = 0; j < 4; j++) {
                uint32_t bhi[2], blo[2];
                ldmx2(bhi, bHi[j] + ko);
                ldmx2(blo, bLo[j] + ko);
#pragma unroll
                for (int i = 0; i < 2; i++) {
                    mma_bf16(acc[i][j], ahi[i], bhi);
                    mma_bf16(acc[i][j], alo[i], bhi);
                    mma_bf16(acc[i][j], ahi[i], blo);
                }
            }
        }

        int2 mj[4];
#pragma unroll
        for (int j = 0; j < 4; j++)
            mj[j] = *reinterpret_cast<const int2*>(mask + b * S + kt * 64 + wn * 32 + j * 8 + 2 * tig);

#pragma unroll
        for (int i = 0; i < 2; i++) {
#pragma unroll
            for (int j = 0; j < 4; j++) {
                float v;
                v = acc[i][j][0] * 0.125f + og[i][0]; acc[i][j][0] = mj[j].x ? v : -1e9f;
                v = acc[i][j][1] * 0.125f + og[i][0]; acc[i][j][1] = mj[j].y ? v : -1e9f;
                v = acc[i][j][2] * 0.125f + og[i][1]; acc[i][j][2] = mj[j].x ? v : -1e9f;
                v = acc[i][j][3] * 0.125f + og[i][1]; acc[i][j][3] = mj[j].y ? v : -1e9f;
            }
        }

#pragma unroll
        for (int i = 0; i < 2; i++) {
#pragma unroll
            for (int hh = 0; hh < 2; hh++) {
                float mt = -1e30f;
#pragma unroll
                for (int j = 0; j < 4; j++)
                    mt = fmaxf(mt, fmaxf(acc[i][j][hh * 2], acc[i][j][hh * 2 + 1]));
                mt = fmaxf(mt, __shfl_xor_sync(0xffffffffu, mt, 1));
                mt = fmaxf(mt, __shfl_xor_sync(0xffffffffu, mt, 2));
                const float mnew = fmaxf(rm[i][hh], mt);
                float st = 0.0f;
#pragma unroll
                for (int j = 0; j < 4; j++)
                    st += __expf(acc[i][j][hh * 2] - mnew) + __expf(acc[i][j][hh * 2 + 1] - mnew);
                st += __shfl_xor_sync(0xffffffffu, st, 1);
                st += __shfl_xor_sync(0xffffffffu, st, 2);
                rs[i][hh] = rs[i][hh] * __expf(rm[i][hh] - mnew) + st;
                rm[i][hh] = mnew;
            }
        }
        __syncthreads();
    }

    if (tig == 0) {
#pragma unroll
        for (int i = 0; i < 2; i++)
#pragma unroll
            for (int hh = 0; hh < 2; hh++) {
                const int r = wm * 32 + i * 16 + g + hh * 8;
                redM[r * 2 + wn] = rm[i][hh];
                redS[r * 2 + wn] = rs[i][hh];
            }
    }
    __syncthreads();
    if (t < 128) {
        const float m0 = redM[t * 2], m1 = redM[t * 2 + 1];
        const float m = fmaxf(m0, m1);
        const float s = redS[t * 2] * __expf(m0 - m) + redS[t * 2 + 1] * __expf(m1 - m);
        rowM[(size_t)bh * S + q0 + t] = m;
        rowInv[(size_t)bh * S + q0 + t] = 1.0f / s;
    }
}

// ============================================================================
// av_fused v2 (FA2-style): M-only warp split (8 warps x 16 rows, full 64-key
// strip per warp). QK accum fragments -> p -> PACKED DIRECTLY into PV
// A-fragments (no P smem, one barrier fewer per tile).
// ============================================================================
namespace {
constexpr int AF_QHI = 0;
constexpr int AF_QLO = 128 * KPS;
constexpr int AF_KHI = 2 * 128 * KPS;
constexpr int AF_KLO = AF_KHI + 64 * KPS;
constexpr int AF_VHI = AF_KLO + 64 * KPS;
constexpr int AF_VLO = AF_VHI + 64 * KPS;
constexpr int AF_RM  = AF_VLO + 64 * KPS;
constexpr int AF_RI  = AF_RM + 128;
constexpr int SMEM_AF = (AF_RI + 128) * 4;     // 74,752 bytes
constexpr int BSTEP = 16 * KPS * 4;            // byte stride between n-tile pairs
}

__global__ void __launch_bounds__(256, 2) av_fused(
    const float* __restrict__ Q, const float* __restrict__ K,
    const float* __restrict__ V,
    const int* __restrict__ mask, const float* __restrict__ is_org,
    const float* __restrict__ Worg, const float* __restrict__ borg,
    const float* __restrict__ rowM, const float* __restrict__ rowInv,
    float* __restrict__ att, float* __restrict__ C)
{
    extern __shared__ uint32_t smu[];
    uint32_t* Qhi = smu + AF_QHI;
    uint32_t* Qlo = smu + AF_QLO;
    uint32_t* Khi = smu + AF_KHI;
    uint32_t* Klo = smu + AF_KLO;
    uint32_t* Vhi = smu + AF_VHI;
    uint32_t* Vlo = smu + AF_VLO;
    float*    Rm  = reinterpret_cast<float*>(smu + AF_RM);
    float*    Ri  = reinterpret_cast<float*>(smu + AF_RI);

    const int t = threadIdx.x, lane = t & 31, wid = t >> 5;   // wid 0..7
    const int g = lane >> 2, tig = lane & 3;
    const int bh = blockIdx.y, b = bh >> 3, h = bh & 7;
    const int q0 = blockIdx.x * 128;

    const float* Qg = Q + ((size_t)(b * S + q0)) * D + h * DK;
    const float* Kg = K + ((size_t)(b * S)) * D + h * DK;
    const float* Vg = V + ((size_t)(b * S)) * D + h * DK;

    if (t < 128) {
        Rm[t] = rowM[(size_t)bh * S + q0 + t];
        Ri[t] = rowInv[(size_t)bh * S + q0 + t];
    }
#pragma unroll
    for (int i = t; i < 2048; i += 256) {
        const int row = i >> 4, c4 = (i & 15) * 4, p = c4 >> 1;
        float4 qv = *reinterpret_cast<const float4*>(Qg + (size_t)row * D + c4);
        uint2 h2, l2;
        split_bf16x2(qv.x, qv.y, h2.x, l2.x);
        split_bf16x2(qv.z, qv.w, h2.y, l2.y);
        *reinterpret_cast<uint2*>(&Qhi[row * KPS + p]) = h2;
        *reinterpret_cast<uint2*>(&Qlo[row * KPS + p]) = l2;
    }

    // A (Q) ldmatrix base: one 16-row m-tile per warp
    const int am = lane >> 3, arm = lane & 7;
    uint32_t aQhi, aQlo;
    {
        const int row = wid * 16 + (am & 1) * 8 + arm;
        const uint32_t off = (uint32_t)(row * KPS + (am >> 1) * 4) * 4u;
        aQhi = smaddr(Qhi) + off;
        aQlo = smaddr(Qlo) + off;
    }
    // B x4 base (two 8-row n-tiles per ldmx4): K and V share the pattern
    uint32_t bKhi, bKlo, bVhi, bVlo;
    {
        const int brow = ((lane >> 4) & 1) * 8 + (lane & 7);
        const int bkp  = ((lane >> 3) & 1) * 4;
        const uint32_t off = (uint32_t)(brow * KPS + bkp) * 4u;
        bKhi = smaddr(Khi) + off; bKlo = smaddr(Klo) + off;
        bVhi = smaddr(Vhi) + off; bVlo = smaddr(Vlo) + off;
    }

    const float worg = __ldg(Worg + h), bog = __ldg(borg + h);
    const int r0 = wid * 16 + g;           // thread's two q-rows: r0, r0+8
    float og0 = __ldg(is_org + b * S + q0 + r0) * worg + bog;
    float og1 = __ldg(is_org + b * S + q0 + r0 + 8) * worg + bog;

    __syncthreads();
    const float M0 = Rm[r0], I0 = Ri[r0];
    const float M1 = Rm[r0 + 8], I1 = Ri[r0 + 8];

    float accAV[8][4] = {};

    for (int kt = 0; kt < 32; kt++) {
        // Load K tile (64x64) + V tile (transposed [d][kp]), bf16-split
#pragma unroll
        for (int i = t; i < 1024; i += 256) {
            const int row = i >> 4, c4 = (i & 15) * 4, p = c4 >> 1;
            float4 kv = *reinterpret_cast<const float4*>(
                Kg + (size_t)(kt * 64 + row) * D + c4);
            uint2 h2, l2;
            split_bf16x2(kv.x, kv.y, h2.x, l2.x);
            split_bf16x2(kv.z, kv.w, h2.y, l2.y);
            *reinterpret_cast<uint2*>(&Khi[row * KPS + p]) = h2;
            *reinterpret_cast<uint2*>(&Klo[row * KPS + p]) = l2;
        }
#pragma unroll
        for (int i = t; i < 512; i += 256) {
            const int dg = i & 15, kp = i >> 4;
            const float* vp = Vg + (size_t)(kt * 64 + 2 * kp) * D + dg * 4;
            float4 va = *reinterpret_cast<const float4*>(vp);
            float4 vb = *reinterpret_cast<const float4*>(vp + D);
            uint32_t hi, lo;
            split_bf16x2(va.x, vb.x, hi, lo);
            Vhi[(dg * 4 + 0) * KPS + kp] = hi; Vlo[(dg * 4 + 0) * KPS + kp] = lo;
            split_bf16x2(va.y, vb.y, hi, lo);
            Vhi[(dg * 4 + 1) * KPS + kp] = hi; Vlo[(dg * 4 + 1) * KPS + kp] = lo;
            split_bf16x2(va.z, vb.z, hi, lo);
            Vhi[(dg * 4 + 2) * KPS + kp] = hi; Vlo[(dg * 4 + 2) * KPS + kp] = lo;
            split_bf16x2(va.w, vb.w, hi, lo);
            Vhi[(dg * 4 + 3) * KPS + kp] = hi; Vlo[(dg * 4 + 3) * KPS + kp] = lo;
        }
        __syncthreads();

        // QK: acc[j] = logits for n-tile j (j = 0..7 over 64 keys)
        float acc[8][4] = {};
#pragma unroll
        for (int ks = 0; ks < 4; ks++) {
            const uint32_t ko = ks * 32u;
            uint32_t ah[4], al[4];
            ldmx4(ah, aQhi + ko);
            ldmx4(al, aQlo + ko);
#pragma unroll
            for (int jp = 0; jp < 4; jp++) {
                uint32_t bhv[4], blv[4];
                ldmx4(bhv, bKhi + jp * BSTEP + ko);
                ldmx4(blv, bKlo + jp * BSTEP + ko);
                mma_bf16(acc[2 * jp],     ah, bhv);
                mma_bf16(acc[2 * jp],     al, bhv);
                mma_bf16(acc[2 * jp],     ah, blv);
                mma_bf16(acc[2 * jp + 1], ah, bhv + 2);
                mma_bf16(acc[2 * jp + 1], al, bhv + 2);
                mma_bf16(acc[2 * jp + 1], ah, blv + 2);
            }
        }

        // Softmax epilogue: p = exp(x - M) * Inv; write p to att; keep in acc
        float* arow0 = &att[((size_t)bh * S + q0 + r0) * S + kt * 64 + 2 * tig];
        float* arow1 = arow0 + 8 * S;
#pragma unroll
        for (int j = 0; j < 8; j++) {
            const int2 mj = *reinterpret_cast<const int2*>(
                mask + b * S + kt * 64 + j * 8 + 2 * tig);
            float x0 = acc[j][0] * 0.125f + og0;
            float x1 = acc[j][1] * 0.125f + og0;
            float x2 = acc[j][2] * 0.125f + og1;
            float x3 = acc[j][3] * 0.125f + og1;
            x0 = mj.x ? x0 : -1e9f;
            x1 = mj.y ? x1 : -1e9f;
            x2 = mj.x ? x2 : -1e9f;
            x3 = mj.y ? x3 : -1e9f;
            const float p0 = __expf(x0 - M0) * I0;
            const float p1 = __expf(x1 - M0) * I0;
            const float p2 = __expf(x2 - M1) * I1;
            const float p3 = __expf(x3 - M1) * I1;
            float2 o;
            o.x = p0; o.y = p1;
            *reinterpret_cast<float2*>(arow0 + j * 8) = o;
            o.x = p2; o.y = p3;
            *reinterpret_cast<float2*>(arow1 + j * 8) = o;
            acc[j][0] = p0; acc[j][1] = p1; acc[j][2] = p2; acc[j][3] = p3;
        }

        // PV: A-frags packed directly from acc (C-frag == A-frag layout)
#pragma unroll
        for (int jj = 0; jj < 4; jj++) {
            uint32_t ph[4], pl[4];
            split_bf16x2(acc[2 * jj][0],     acc[2 * jj][1],     ph[0], pl[0]);
            split_bf16x2(acc[2 * jj][2],     acc[2 * jj][3],     ph[1], pl[1]);
            split_bf16x2(acc[2 * jj + 1][0], acc[2 * jj + 1][1], ph[2], pl[2]);
            split_bf16x2(acc[2 * jj + 1][2], acc[2 * jj + 1][3], ph[3], pl[3]);
            const uint32_t ko = jj * 32u;
#pragma unroll
            for (int dp = 0; dp < 4; dp++) {
                uint32_t vh[4], vl[4];
                ldmx4(vh, bVhi + dp * BSTEP + ko);
                ldmx4(vl, bVlo + dp * BSTEP + ko);
                mma_bf16(accAV[2 * dp],     ph, vh);
                mma_bf16(accAV[2 * dp],     pl, vh);
                mma_bf16(accAV[2 * dp],     ph, vl);
                mma_bf16(accAV[2 * dp + 1], ph, vh + 2);
                mma_bf16(accAV[2 * dp + 1], pl, vh + 2);
                mma_bf16(accAV[2 * dp + 1], ph, vl + 2);
            }
        }
        __syncthreads();
    }

    // Store context C
#pragma unroll
    for (int dj = 0; dj < 8; dj++) {
        const int col = h * DK + dj * 8 + 2 * tig;
        float2 o;
        o.x = accAV[dj][0]; o.y = accAV[dj][1];
        *reinterpret_cast<float2*>(&C[(size_t)(b * S + q0 + r0) * D + col]) = o;
        o.x = accAV[dj][2]; o.y = accAV[dj][3];
        *reinterpret_cast<float2*>(&C[(size_t)(b * S + q0 + r0 + 8) * D + col]) = o;
    }
}

// ---------------------------------------------------------------------------
extern "C" void kernel_launch(void* const* d_in, const int* in_sizes, int n_in,
                              void* d_out, int out_size)
{
    const float* query = (const float*)d_in[0];
    const float* key   = (const float*)d_in[1];
    const float* value = (const float*)d_in[2];
    const int*   mask  = (const int*)d_in[3];
    const float* isog  = (const float*)d_in[4];
    const float* Wq    = (const float*)d_in[5];
    const float* bq    = (const float*)d_in[6];
    const float* Wk    = (const float*)d_in[7];
    const float* bk    = (const float*)d_in[8];
    const float* Wv    = (const float*)d_in[9];
    const float* bv    = (const float*)d_in[10];
    const float* Wo    = (const float*)d_in[11];
    const float* bo    = (const float*)d_in[12];
    const float* Worg  = (const float*)d_in[13];
    const float* borg  = (const float*)d_in[14];

    float* out = (float*)d_out;

    float *qbuf, *kbuf, *vbuf, *cbuf, *rowM, *rowInv;
    cudaGetSymbolAddress((void**)&qbuf, g_Q);
    cudaGetSymbolAddress((void**)&kbuf, g_K);
    cudaGetSymbolAddress((void**)&vbuf, g_V);
    cudaGetSymbolAddress((void**)&cbuf, g_C);
    cudaGetSymbolAddress((void**)&rowM, g_rowM);
    cudaGetSymbolAddress((void**)&rowInv, g_rowInv);

    const long long OUT_MAIN = (long long)B * S * D;
    const long long ATT_SZ   = (long long)B * H * S * S;
    float* att;
    if ((long long)out_size >= OUT_MAIN + ATT_SZ) {
        att = out + OUT_MAIN;
    } else {
        cudaGetSymbolAddress((void**)&att, g_att);
    }

    static bool attr_done = false;
    if (!attr_done) {
        cudaFuncSetAttribute(gemm_mma,  cudaFuncAttributeMaxDynamicSharedMemorySize, SMEM_GEMM);
        cudaFuncSetAttribute(stats_mma, cudaFuncAttributeMaxDynamicSharedMemorySize, SMEM_STATS);
        cudaFuncSetAttribute(av_fused,  cudaFuncAttributeMaxDynamicSharedMemorySize, SMEM_AF);
        attr_done = true;
    }

    dim3 gg(4, 64);
    gemm_mma<<<gg, 256, SMEM_GEMM>>>(query, Wq, bq, qbuf);
    gemm_mma<<<gg, 256, SMEM_GEMM>>>(key,   Wk, bk, kbuf);
    gemm_mma<<<gg, 256, SMEM_GEMM>>>(value, Wv, bv, vbuf);

    dim3 gf(S / 128, B * H);
    stats_mma<<<gf, 256, SMEM_STATS>>>(qbuf, kbuf, mask, isog, Worg, borg, rowM, rowInv);

    av_fused<<<gf, 256, SMEM_AF>>>(qbuf, kbuf, vbuf, mask, isog, Worg, borg,
                                   rowM, rowInv, att, cbuf);

    gemm_mma<<<gg, 256, SMEM_GEMM>>>(cbuf, Wo, bo, out);
}

// round 11
// speedup vs baseline: 1.7298x; 1.0017x over previous
#include <cuda_runtime.h>
#include <cstdint>

namespace {
constexpr int B = 4, S = 2048, D = 512, H = 8, DK = 64;
}

// Scratch (allocation-free rule: __device__ globals)
__device__ float g_Q[(size_t)B * S * D];
__device__ float g_K[(size_t)B * S * D];
__device__ float g_V[(size_t)B * S * D];
__device__ float g_C[(size_t)B * S * D];
__device__ float g_att[(size_t)B * H * S * S];
__device__ float g_rowM[(size_t)B * H * S];
__device__ float g_rowInv[(size_t)B * H * S];

// ============================================================================
// bf16 split, MMA, ldmatrix helpers (portable PTX — works on compute_103)
// ============================================================================
__device__ __forceinline__ void split_bf16x2(float x0, float x1, uint32_t& hi, uint32_t& lo) {
    asm("cvt.rn.bf16x2.f32 %0, %1, %2;" : "=r"(hi) : "f"(x1), "f"(x0));
    const float h0 = __uint_as_float(hi << 16);
    const float h1 = __uint_as_float(hi & 0xFFFF0000u);
    asm("cvt.rn.bf16x2.f32 %0, %1, %2;" : "=r"(lo) : "f"(x1 - h1), "f"(x0 - h0));
}
__device__ __forceinline__ void mma_bf16(float c[4], const uint32_t a[4], const uint32_t b[2]) {
    asm volatile(
        "mma.sync.aligned.m16n8k16.row.col.f32.bf16.bf16.f32 "
        "{%0,%1,%2,%3}, {%4,%5,%6,%7}, {%8,%9}, {%0,%1,%2,%3};"
        : "+f"(c[0]), "+f"(c[1]), "+f"(c[2]), "+f"(c[3])
        : "r"(a[0]), "r"(a[1]), "r"(a[2]), "r"(a[3]), "r"(b[0]), "r"(b[1]));
}
__device__ __forceinline__ void ldmx4(uint32_t r[4], uint32_t addr) {
    asm volatile("ldmatrix.sync.aligned.m8n8.x4.shared.b16 {%0,%1,%2,%3}, [%4];"
                 : "=r"(r[0]), "=r"(r[1]), "=r"(r[2]), "=r"(r[3]) : "r"(addr));
}
__device__ __forceinline__ void ldmx2(uint32_t r[2], uint32_t addr) {
    asm volatile("ldmatrix.sync.aligned.m8n8.x2.shared.b16 {%0,%1}, [%2];"
                 : "=r"(r[0]), "=r"(r[1]) : "r"(addr));
}
__device__ __forceinline__ uint32_t smaddr(const void* p) {
    return (uint32_t)__cvta_generic_to_shared(p);
}

namespace {
constexpr int KPS = 36;   // bf16x2-pair stride (padded; conflict-free)
}

// ============================================================================
// Projection GEMM (bf16 3-term): Y[M,512] = X @ W^T + bias  (unchanged)
// ============================================================================
namespace {
constexpr int GM_XHI = 0;
constexpr int GM_XLO = 128 * KPS;
constexpr int GM_WHI = 2 * 128 * KPS;
constexpr int GM_WLO = 3 * 128 * KPS;
constexpr int SMEM_GEMM = 4 * 128 * KPS * 4;     // 73,728 bytes
}

__global__ void __launch_bounds__(256, 2) gemm_mma(
    const float* __restrict__ X, const float* __restrict__ W,
    const float* __restrict__ bias, float* __restrict__ Y)
{
    extern __shared__ uint32_t smu[];
    uint32_t* Xhi = smu + GM_XHI;
    uint32_t* Xlo = smu + GM_XLO;
    uint32_t* Whi = smu + GM_WHI;
    uint32_t* Wlo = smu + GM_WLO;

    const int t = threadIdx.x, lane = t & 31, wid = t >> 5;
    const int g = lane >> 2, tig = lane & 3;
    const int wm = wid & 1, wn = wid >> 1;
    const int m0 = blockIdx.y * 128, n0 = blockIdx.x * 128;

    const int am = lane >> 3, arm = lane & 7;
    const int bmat = (lane >> 3) & 1, brm = lane & 7;
    uint32_t aHi[4], aLo[4], bHi[4], bLo[4];
#pragma unroll
    for (int i = 0; i < 4; i++) {
        const int row = wm * 64 + i * 16 + (am & 1) * 8 + arm;
        const uint32_t off = (uint32_t)(row * KPS + (am >> 1) * 4) * 4u;
        aHi[i] = smaddr(Xhi) + off;
        aLo[i] = smaddr(Xlo) + off;
    }
#pragma unroll
    for (int j = 0; j < 4; j++) {
        const int row = wn * 32 + j * 8 + brm;
        const uint32_t off = (uint32_t)(row * KPS + bmat * 4) * 4u;
        bHi[j] = smaddr(Whi) + off;
        bLo[j] = smaddr(Wlo) + off;
    }

    float acc[4][4][4] = {};

    for (int kc = 0; kc < 512; kc += 64) {
#pragma unroll
        for (int i = t; i < 2048; i += 256) {
            const int row = i >> 4, c4 = (i & 15) * 4, p = c4 >> 1;
            float4 xv = *reinterpret_cast<const float4*>(&X[(size_t)(m0 + row) * 512 + kc + c4]);
            float4 wv = *reinterpret_cast<const float4*>(&W[(size_t)(n0 + row) * 512 + kc + c4]);
            uint2 h, l;
            split_bf16x2(xv.x, xv.y, h.x, l.x);
            split_bf16x2(xv.z, xv.w, h.y, l.y);
            *reinterpret_cast<uint2*>(&Xhi[row * KPS + p]) = h;
            *reinterpret_cast<uint2*>(&Xlo[row * KPS + p]) = l;
            split_bf16x2(wv.x, wv.y, h.x, l.x);
            split_bf16x2(wv.z, wv.w, h.y, l.y);
            *reinterpret_cast<uint2*>(&Whi[row * KPS + p]) = h;
            *reinterpret_cast<uint2*>(&Wlo[row * KPS + p]) = l;
        }
        __syncthreads();

#pragma unroll
        for (int ks = 0; ks < 4; ks++) {
            const uint32_t ko = ks * 32u;
            uint32_t ahi[4][4], alo[4][4];
#pragma unroll
            for (int i = 0; i < 4; i++) {
                ldmx4(ahi[i], aHi[i] + ko);
                ldmx4(alo[i], aLo[i] + ko);
            }
#pragma unroll
            for (int j = 0; j < 4; j++) {
                uint32_t bhi[2], blo[2];
                ldmx2(bhi, bHi[j] + ko);
                ldmx2(blo, bLo[j] + ko);
#pragma unroll
                for (int i = 0; i < 4; i++) {
                    mma_bf16(acc[i][j], ahi[i], bhi);
                    mma_bf16(acc[i][j], alo[i], bhi);
                    mma_bf16(acc[i][j], ahi[i], blo);
                }
            }
        }
        __syncthreads();
    }

#pragma unroll
    for (int i = 0; i < 4; i++) {
        const int row0 = m0 + wm * 64 + i * 16 + g;
#pragma unroll
        for (int j = 0; j < 4; j++) {
            const int col = n0 + wn * 32 + j * 8 + 2 * tig;
            const float b0 = __ldg(bias + col), b1 = __ldg(bias + col + 1);
            float2 o;
            o.x = acc[i][j][0] + b0; o.y = acc[i][j][1] + b1;
            *reinterpret_cast<float2*>(&Y[(size_t)row0 * 512 + col]) = o;
            o.x = acc[i][j][2] + b0; o.y = acc[i][j][3] + b1;
            *reinterpret_cast<float2*>(&Y[(size_t)(row0 + 8) * 512 + col]) = o;
        }
    }
}

// ============================================================================
// stats_mma: online (max, sumexp) over streamed k-tiles -> rowM, rowInv
// (unchanged from R9)
// ============================================================================
namespace {
constexpr int ST_QHI = 0;
constexpr int ST_QLO = 128 * KPS;
constexpr int ST_KHI = 2 * 128 * KPS;
constexpr int ST_KLO = ST_KHI + 64 * KPS;
constexpr int ST_RED = ST_KLO + 64 * KPS;
constexpr int SMEM_STATS = (ST_RED + 512) * 4;      // 57,344 bytes
}

__global__ void __launch_bounds__(256, 2) stats_mma(
    const float* __restrict__ Q, const float* __restrict__ K,
    const int* __restrict__ mask, const float* __restrict__ is_org,
    const float* __restrict__ Worg, const float* __restrict__ borg,
    float* __restrict__ rowM, float* __restrict__ rowInv)
{
    extern __shared__ uint32_t smu[];
    uint32_t* Qhi = smu + ST_QHI;
    uint32_t* Qlo = smu + ST_QLO;
    uint32_t* Khi = smu + ST_KHI;
    uint32_t* Klo = smu + ST_KLO;
    float* redM = reinterpret_cast<float*>(smu + ST_RED);
    float* redS = redM + 256;

    const int t = threadIdx.x, lane = t & 31, wid = t >> 5;
    const int g = lane >> 2, tig = lane & 3;
    const int wm = wid & 3, wn = wid >> 2;
    const int bh = blockIdx.y, b = bh >> 3, h = bh & 7;
    const int q0 = blockIdx.x * 128;

    const float* Qg = Q + ((size_t)(b * S + q0)) * D + h * DK;
    const float* Kg = K + ((size_t)(b * S)) * D + h * DK;

#pragma unroll
    for (int i = t; i < 2048; i += 256) {
        const int row = i >> 4, c4 = (i & 15) * 4, p = c4 >> 1;
        float4 qv = *reinterpret_cast<const float4*>(Qg + (size_t)row * D + c4);
        uint2 h2, l2;
        split_bf16x2(qv.x, qv.y, h2.x, l2.x);
        split_bf16x2(qv.z, qv.w, h2.y, l2.y);
        *reinterpret_cast<uint2*>(&Qhi[row * KPS + p]) = h2;
        *reinterpret_cast<uint2*>(&Qlo[row * KPS + p]) = l2;
    }

    const int am = lane >> 3, arm = lane & 7;
    const int bmat = (lane >> 3) & 1, brm = lane & 7;
    uint32_t aHi[2], aLo[2], bHi[4], bLo[4];
#pragma unroll
    for (int i = 0; i < 2; i++) {
        const int row = wm * 32 + i * 16 + (am & 1) * 8 + arm;
        const uint32_t off = (uint32_t)(row * KPS + (am >> 1) * 4) * 4u;
        aHi[i] = smaddr(Qhi) + off;
        aLo[i] = smaddr(Qlo) + off;
    }
#pragma unroll
    for (int j = 0; j < 4; j++) {
        const int row = wn * 32 + j * 8 + brm;
        const uint32_t off = (uint32_t)(row * KPS + bmat * 4) * 4u;
        bHi[j] = smaddr(Khi) + off;
        bLo[j] = smaddr(Klo) + off;
    }

    const float worg = __ldg(Worg + h), bog = __ldg(borg + h);
    float og[2][2];
#pragma unroll
    for (int i = 0; i < 2; i++)
#pragma unroll
        for (int hh = 0; hh < 2; hh++)
            og[i][hh] = __ldg(is_org + b * S + q0 + wm * 32 + i * 16 + g + hh * 8) * worg + bog;

    float rm[2][2], rs[2][2];
#pragma unroll
    for (int i = 0; i < 2; i++)
#pragma unroll
        for (int hh = 0; hh < 2; hh++) { rm[i][hh] = -1e30f; rs[i][hh] = 0.0f; }

    for (int kt = 0; kt < 32; kt++) {
#pragma unroll
        for (int i = t; i < 1024; i += 256) {
            const int row = i >> 4, c4 = (i & 15) * 4, p = c4 >> 1;
            float4 kv = *reinterpret_cast<const float4*>(
                Kg + (size_t)(kt * 64 + row) * D + c4);
            uint2 h2, l2;
            split_bf16x2(kv.x, kv.y, h2.x, l2.x);
            split_bf16x2(kv.z, kv.w, h2.y, l2.y);
            *reinterpret_cast<uint2*>(&Khi[row * KPS + p]) = h2;
            *reinterpret_cast<uint2*>(&Klo[row * KPS + p]) = l2;
        }
        __syncthreads();

        float acc[2][4][4] = {};
#pragma unroll
        for (int ks = 0; ks < 4; ks++) {
            const uint32_t ko = ks * 32u;
            uint32_t ahi[2][4], alo[2][4];
#pragma unroll
            for (int i = 0; i < 2; i++) { ldmx4(ahi[i], aHi[i] + ko); ldmx4(alo[i], aLo[i] + ko); }
#pragma unroll
            for (int j = 0; j < 4; j++) {
                uint32_t bhi[2], blo[2];
                ldmx2(bhi, bHi[j] + ko);
                ldmx2(blo, bLo[j] + ko);
#pragma unroll
                for (int i = 0; i < 2; i++) {
                    mma_bf16(acc[i][j], ahi[i], bhi);
                    mma_bf16(acc[i][j], alo[i], bhi);
                    mma_bf16(acc[i][j], ahi[i], blo);
                }
            }
        }

        int2 mj[4];
#pragma unroll
        for (int j = 0; j < 4; j++)
            mj[j] = *reinterpret_cast<const int2*>(mask + b * S + kt * 64 + wn * 32 + j * 8 + 2 * tig);

#pragma unroll
        for (int i = 0; i < 2; i++) {
#pragma unroll
            for (int j = 0; j < 4; j++) {
                float v;
                v = acc[i][j][0] * 0.125f + og[i][0]; acc[i][j][0] = mj[j].x ? v : -1e9f;
                v = acc[i][j][1] * 0.125f + og[i][0]; acc[i][j][1] = mj[j].y ? v : -1e9f;
                v = acc[i][j][2] * 0.125f + og[i][1]; acc[i][j][2] = mj[j].x ? v : -1e9f;
                v = acc[i][j][3] * 0.125f + og[i][1]; acc[i][j][3] = mj[j].y ? v : -1e9f;
            }
        }

#pragma unroll
        for (int i = 0; i < 2; i++) {
#pragma unroll
            for (int hh = 0; hh < 2; hh++) {
                float mt = -1e30f;
#pragma unroll
                for (int j = 0; j < 4; j++)
                    mt = fmaxf(mt, fmaxf(acc[i][j][hh * 2], acc[i][j][hh * 2 + 1]));
                mt = fmaxf(mt, __shfl_xor_sync(0xffffffffu, mt, 1));
                mt = fmaxf(mt, __shfl_xor_sync(0xffffffffu, mt, 2));
                const float mnew = fmaxf(rm[i][hh], mt);
                float st = 0.0f;
#pragma unroll
                for (int j = 0; j < 4; j++)
                    st += __expf(acc[i][j][hh * 2] - mnew) + __expf(acc[i][j][hh * 2 + 1] - mnew);
                st += __shfl_xor_sync(0xffffffffu, st, 1);
                st += __shfl_xor_sync(0xffffffffu, st, 2);
                rs[i][hh] = rs[i][hh] * __expf(rm[i][hh] - mnew) + st;
                rm[i][hh] = mnew;
            }
        }
        __syncthreads();
    }

    if (tig == 0) {
#pragma unroll
        for (int i = 0; i < 2; i++)
#pragma unroll
            for (int hh = 0; hh < 2; hh++) {
                const int r = wm * 32 + i * 16 + g + hh * 8;
                redM[r * 2 + wn] = rm[i][hh];
                redS[r * 2 + wn] = rs[i][hh];
            }
    }
    __syncthreads();
    if (t < 128) {
        const float m0 = redM[t * 2], m1 = redM[t * 2 + 1];
        const float m = fmaxf(m0, m1);
        const float s = redS[t * 2] * __expf(m0 - m) + redS[t * 2 + 1] * __expf(m1 - m);
        rowM[(size_t)bh * S + q0 + t] = m;
        rowInv[(size_t)bh * S + q0 + t] = 1.0f / s;
    }
}

// ============================================================================
// av_fused v2 (FA2-style): M-only warp split (8 warps x 16 rows, full 64-key
// strip per warp). QK accum fragments -> p -> PACKED DIRECTLY into PV
// A-fragments (no P smem, one barrier fewer per tile).
// ============================================================================
namespace {
constexpr int AF_QHI = 0;
constexpr int AF_QLO = 128 * KPS;
constexpr int AF_KHI = 2 * 128 * KPS;
constexpr int AF_KLO = AF_KHI + 64 * KPS;
constexpr int AF_VHI = AF_KLO + 64 * KPS;
constexpr int AF_VLO = AF_VHI + 64 * KPS;
constexpr int AF_RM  = AF_VLO + 64 * KPS;
constexpr int AF_RI  = AF_RM + 128;
constexpr int SMEM_AF = (AF_RI + 128) * 4;     // 74,752 bytes
constexpr int BSTEP = 16 * KPS * 4;            // byte stride between n-tile pairs
}

__global__ void __launch_bounds__(256, 2) av_fused(
    const float* __restrict__ Q, const float* __restrict__ K,
    const float* __restrict__ V,
    const int* __restrict__ mask, const float* __restrict__ is_org,
    const float* __restrict__ Worg, const float* __restrict__ borg,
    const float* __restrict__ rowM, const float* __restrict__ rowInv,
    float* __restrict__ att, float* __restrict__ C)
{
    extern __shared__ uint32_t smu[];
    uint32_t* Qhi = smu + AF_QHI;
    uint32_t* Qlo = smu + AF_QLO;
    uint32_t* Khi = smu + AF_KHI;
    uint32_t* Klo = smu + AF_KLO;
    uint32_t* Vhi = smu + AF_VHI;
    uint32_t* Vlo = smu + AF_VLO;
    float*    Rm  = reinterpret_cast<float*>(smu + AF_RM);
    float*    Ri  = reinterpret_cast<float*>(smu + AF_RI);

    const int t = threadIdx.x, lane = t & 31, wid = t >> 5;   // wid 0..7
    const int g = lane >> 2, tig = lane & 3;
    const int bh = blockIdx.y, b = bh >> 3, h = bh & 7;
    const int q0 = blockIdx.x * 128;

    const float* Qg = Q + ((size_t)(b * S + q0)) * D + h * DK;
    const float* Kg = K + ((size_t)(b * S)) * D + h * DK;
    const float* Vg = V + ((size_t)(b * S)) * D + h * DK;

    if (t < 128) {
        Rm[t] = rowM[(size_t)bh * S + q0 + t];
        Ri[t] = rowInv[(size_t)bh * S + q0 + t];
    }
#pragma unroll
    for (int i = t; i < 2048; i += 256) {
        const int row = i >> 4, c4 = (i & 15) * 4, p = c4 >> 1;
        float4 qv = *reinterpret_cast<const float4*>(Qg + (size_t)row * D + c4);
        uint2 h2, l2;
        split_bf16x2(qv.x, qv.y, h2.x, l2.x);
        split_bf16x2(qv.z, qv.w, h2.y, l2.y);
        *reinterpret_cast<uint2*>(&Qhi[row * KPS + p]) = h2;
        *reinterpret_cast<uint2*>(&Qlo[row * KPS + p]) = l2;
    }

    // A (Q) ldmatrix base: one 16-row m-tile per warp
    const int am = lane >> 3, arm = lane & 7;
    uint32_t aQhi, aQlo;
    {
        const int row = wid * 16 + (am & 1) * 8 + arm;
        const uint32_t off = (uint32_t)(row * KPS + (am >> 1) * 4) * 4u;
        aQhi = smaddr(Qhi) + off;
        aQlo = smaddr(Qlo) + off;
    }
    // B x4 base (two 8-row n-tiles per ldmx4): K and V share the pattern
    uint32_t bKhi, bKlo, bVhi, bVlo;
    {
        const int brow = ((lane >> 4) & 1) * 8 + (lane & 7);
        const int bkp  = ((lane >> 3) & 1) * 4;
        const uint32_t off = (uint32_t)(brow * KPS + bkp) * 4u;
        bKhi = smaddr(Khi) + off; bKlo = smaddr(Klo) + off;
        bVhi = smaddr(Vhi) + off; bVlo = smaddr(Vlo) + off;
    }

    const float worg = __ldg(Worg + h), bog = __ldg(borg + h);
    const int r0 = wid * 16 + g;           // thread's two q-rows: r0, r0+8
    float og0 = __ldg(is_org + b * S + q0 + r0) * worg + bog;
    float og1 = __ldg(is_org + b * S + q0 + r0 + 8) * worg + bog;

    __syncthreads();
    const float M0 = Rm[r0], I0 = Ri[r0];
    const float M1 = Rm[r0 + 8], I1 = Ri[r0 + 8];

    float accAV[8][4] = {};

    for (int kt = 0; kt < 32; kt++) {
        // Load K tile (64x64) + V tile (transposed [d][kp]), bf16-split
#pragma unroll
        for (int i = t; i < 1024; i += 256) {
            const int row = i >> 4, c4 = (i & 15) * 4, p = c4 >> 1;
            float4 kv = *reinterpret_cast<const float4*>(
                Kg + (size_t)(kt * 64 + row) * D + c4);
            uint2 h2, l2;
            split_bf16x2(kv.x, kv.y, h2.x, l2.x);
            split_bf16x2(kv.z, kv.w, h2.y, l2.y);
            *reinterpret_cast<uint2*>(&Khi[row * KPS + p]) = h2;
            *reinterpret_cast<uint2*>(&Klo[row * KPS + p]) = l2;
        }
#pragma unroll
        for (int i = t; i < 512; i += 256) {
            const int dg = i & 15, kp = i >> 4;
            const float* vp = Vg + (size_t)(kt * 64 + 2 * kp) * D + dg * 4;
            float4 va = *reinterpret_cast<const float4*>(vp);
            float4 vb = *reinterpret_cast<const float4*>(vp + D);
            uint32_t hi, lo;
            split_bf16x2(va.x, vb.x, hi, lo);
            Vhi[(dg * 4 + 0) * KPS + kp] = hi; Vlo[(dg * 4 + 0) * KPS + kp] = lo;
            split_bf16x2(va.y, vb.y, hi, lo);
            Vhi[(dg * 4 + 1) * KPS + kp] = hi; Vlo[(dg * 4 + 1) * KPS + kp] = lo;
            split_bf16x2(va.z, vb.z, hi, lo);
            Vhi[(dg * 4 + 2) * KPS + kp] = hi; Vlo[(dg * 4 + 2) * KPS + kp] = lo;
            split_bf16x2(va.w, vb.w, hi, lo);
            Vhi[(dg * 4 + 3) * KPS + kp] = hi; Vlo[(dg * 4 + 3) * KPS + kp] = lo;
        }
        __syncthreads();

        // QK: acc[j] = logits for n-tile j (j = 0..7 over 64 keys)
        float acc[8][4] = {};
#pragma unroll
        for (int ks = 0; ks < 4; ks++) {
            const uint32_t ko = ks * 32u;
            uint32_t ah[4], al[4];
            ldmx4(ah, aQhi + ko);
            ldmx4(al, aQlo + ko);
#pragma unroll
            for (int jp = 0; jp < 4; jp++) {
                uint32_t bhv[4], blv[4];
                ldmx4(bhv, bKhi + jp * BSTEP + ko);
                ldmx4(blv, bKlo + jp * BSTEP + ko);
                mma_bf16(acc[2 * jp],     ah, bhv);
                mma_bf16(acc[2 * jp],     al, bhv);
                mma_bf16(acc[2 * jp],     ah, blv);
                mma_bf16(acc[2 * jp + 1], ah, bhv + 2);
                mma_bf16(acc[2 * jp + 1], al, bhv + 2);
                mma_bf16(acc[2 * jp + 1], ah, blv + 2);
            }
        }

        // Softmax epilogue: p = exp(x - M) * Inv; write p to att; keep in acc
        float* arow0 = &att[((size_t)bh * S + q0 + r0) * S + kt * 64 + 2 * tig];
        float* arow1 = arow0 + 8 * S;
#pragma unroll
        for (int j = 0; j < 8; j++) {
            const int2 mj = *reinterpret_cast<const int2*>(
                mask + b * S + kt * 64 + j * 8 + 2 * tig);
            float x0 = acc[j][0] * 0.125f + og0;
            float x1 = acc[j][1] * 0.125f + og0;
            float x2 = acc[j][2] * 0.125f + og1;
            float x3 = acc[j][3] * 0.125f + og1;
            x0 = mj.x ? x0 : -1e9f;
            x1 = mj.y ? x1 : -1e9f;
            x2 = mj.x ? x2 : -1e9f;
            x3 = mj.y ? x3 : -1e9f;
            const float p0 = __expf(x0 - M0) * I0;
            const float p1 = __expf(x1 - M0) * I0;
            const float p2 = __expf(x2 - M1) * I1;
            const float p3 = __expf(x3 - M1) * I1;
            float2 o;
            o.x = p0; o.y = p1;
            *reinterpret_cast<float2*>(arow0 + j * 8) = o;
            o.x = p2; o.y = p3;
            *reinterpret_cast<float2*>(arow1 + j * 8) = o;
            acc[j][0] = p0; acc[j][1] = p1; acc[j][2] = p2; acc[j][3] = p3;
        }

        // PV: A-frags packed directly from acc (C-frag == A-frag layout)
#pragma unroll
        for (int jj = 0; jj < 4; jj++) {
            uint32_t ph[4], pl[4];
            split_bf16x2(acc[2 * jj][0],     acc[2 * jj][1],     ph[0], pl[0]);
            split_bf16x2(acc[2 * jj][2],     acc[2 * jj][3],     ph[1], pl[1]);
            split_bf16x2(acc[2 * jj + 1][0], acc[2 * jj + 1][1], ph[2], pl[2]);
            split_bf16x2(acc[2 * jj + 1][2], acc[2 * jj + 1][3], ph[3], pl[3]);
            const uint32_t ko = jj * 32u;
#pragma unroll
            for (int dp = 0; dp < 4; dp++) {
                uint32_t vh[4], vl[4];
                ldmx4(vh, bVhi + dp * BSTEP + ko);
                ldmx4(vl, bVlo + dp * BSTEP + ko);
                mma_bf16(accAV[2 * dp],     ph, vh);
                mma_bf16(accAV[2 * dp],     pl, vh);
                mma_bf16(accAV[2 * dp],     ph, vl);
                mma_bf16(accAV[2 * dp + 1], ph, vh + 2);
                mma_bf16(accAV[2 * dp + 1], pl, vh + 2);
                mma_bf16(accAV[2 * dp + 1], ph, vl + 2);
            }
        }
        __syncthreads();
    }

    // Store context C
#pragma unroll
    for (int dj = 0; dj < 8; dj++) {
        const int col = h * DK + dj * 8 + 2 * tig;
        float2 o;
        o.x = accAV[dj][0]; o.y = accAV[dj][1];
        *reinterpret_cast<float2*>(&C[(size_t)(b * S + q0 + r0) * D + col]) = o;
        o.x = accAV[dj][2]; o.y = accAV[dj][3];
        *reinterpret_cast<float2*>(&C[(size_t)(b * S + q0 + r0 + 8) * D + col]) = o;
    }
}

// ---------------------------------------------------------------------------
extern "C" void kernel_launch(void* const* d_in, const int* in_sizes, int n_in,
                              void* d_out, int out_size)
{
    const float* query = (const float*)d_in[0];
    const float* key   = (const float*)d_in[1];
    const float* value = (const float*)d_in[2];
    const int*   mask  = (const int*)d_in[3];
    const float* isog  = (const float*)d_in[4];
    const float* Wq    = (const float*)d_in[5];
    const float* bq    = (const float*)d_in[6];
    const float* Wk    = (const float*)d_in[7];
    const float* bk    = (const float*)d_in[8];
    const float* Wv    = (const float*)d_in[9];
    const float* bv    = (const float*)d_in[10];
    const float* Wo    = (const float*)d_in[11];
    const float* bo    = (const float*)d_in[12];
    const float* Worg  = (const float*)d_in[13];
    const float* borg  = (const float*)d_in[14];

    float* out = (float*)d_out;

    float *qbuf, *kbuf, *vbuf, *cbuf, *rowM, *rowInv;
    cudaGetSymbolAddress((void**)&qbuf, g_Q);
    cudaGetSymbolAddress((void**)&kbuf, g_K);
    cudaGetSymbolAddress((void**)&vbuf, g_V);
    cudaGetSymbolAddress((void**)&cbuf, g_C);
    cudaGetSymbolAddress((void**)&rowM, g_rowM);
    cudaGetSymbolAddress((void**)&rowInv, g_rowInv);

    const long long OUT_MAIN = (long long)B * S * D;
    const long long ATT_SZ   = (long long)B * H * S * S;
    float* att;
    if ((long long)out_size >= OUT_MAIN + ATT_SZ) {
        att = out + OUT_MAIN;
    } else {
        cudaGetSymbolAddress((void**)&att, g_att);
    }

    static bool attr_done = false;
    if (!attr_done) {
        cudaFuncSetAttribute(gemm_mma,  cudaFuncAttributeMaxDynamicSharedMemorySize, SMEM_GEMM);
        cudaFuncSetAttribute(stats_mma, cudaFuncAttributeMaxDynamicSharedMemorySize, SMEM_STATS);
        cudaFuncSetAttribute(av_fused,  cudaFuncAttributeMaxDynamicSharedMemorySize, SMEM_AF);
        attr_done = true;
    }

    dim3 gg(4, 64);
    gemm_mma<<<gg, 256, SMEM_GEMM>>>(query, Wq, bq, qbuf);
    gemm_mma<<<gg, 256, SMEM_GEMM>>>(key,   Wk, bk, kbuf);
    gemm_mma<<<gg, 256, SMEM_GEMM>>>(value, Wv, bv, vbuf);

    dim3 gf(S / 128, B * H);
    stats_mma<<<gf, 256, SMEM_STATS>>>(qbuf, kbuf, mask, isog, Worg, borg, rowM, rowInv);

    av_fused<<<gf, 256, SMEM_AF>>>(qbuf, kbuf, vbuf, mask, isog, Worg, borg,
                                   rowM, rowInv, att, cbuf);

    gemm_mma<<<gg, 256, SMEM_GEMM>>>(cbuf, Wo, bo, out);
}